// round 4
// baseline (speedup 1.0000x reference)
#include <cuda_runtime.h>
#include <cuda_fp8.h>
#include <cuda_bf16.h>
#include <cstdint>

// ============================================================================
// FineGrainedFP8SwiGLUMLP — Round 3: e4m3 mma.sync.m16n8k32 (sm_89-baseline
// ISA, compiles at compute_103) with per-128-K fp32 promotion.
// Products e4m3 x e4m3 are exact; promotion scales applied in fp32 FFMA.
//
//   detect      : classify fp8-weight storage (raw e4m3 bytes vs fp32)
//   norm_w      : weights -> contiguous e4m3 bytes (copy or fp32->fp8)
//   fq_x        : x -> e4m3 bytes + per-(row,128grp) fp32 scale (bit-exact)
//   gemm_fp8    : C = Aq @ Bq^T, fp8 MMA per 128-K block, promote with sA*sW
//   combine_fq  : hidden = fq(silu(gate)*up) -> e4m3 bytes + scales
// ============================================================================

namespace {

constexpr int MM = 4096, HH = 4096, II = 14336, QB = 128;
constexpr float FP8_MAX = 448.0f;
constexpr int STAGES = 4;
constexpr int STAGE_B = 32768;                   // 16KB A + 16KB B (fp8 128x128)
constexpr int SMEM_SZ = STAGES * STAGE_B;        // 128 KB

// ------------------------------- scratch -----------------------------------
__device__ int     g_flag;
__device__ uint8_t g_xq[(size_t)MM * HH];
__device__ float   g_xs[(size_t)MM * (HH / QB)];
__device__ uint8_t g_gw[(size_t)II * HH];
__device__ uint8_t g_uw[(size_t)II * HH];
__device__ uint8_t g_dw[(size_t)HH * II];
__device__ float   g_gate[(size_t)MM * II];
__device__ float   g_up[(size_t)MM * II];
__device__ uint8_t g_hq[(size_t)MM * II];
__device__ float   g_hs[(size_t)MM * (II / QB)];

// --------------------------- PTX helpers -----------------------------------
__device__ __forceinline__ uint32_t smem_u32(const void* p) {
    uint32_t a;
    asm("{ .reg .u64 t; cvta.to.shared.u64 t, %1; cvt.u32.u64 %0, t; }" : "=r"(a) : "l"(p));
    return a;
}
__device__ __forceinline__ void cp16(uint32_t dst, const void* src) {
    asm volatile("cp.async.cg.shared.global [%0], [%1], 16;" :: "r"(dst), "l"(src));
}
__device__ __forceinline__ void ldsm4(uint32_t* r, uint32_t a) {
    asm volatile("ldmatrix.sync.aligned.m8n8.x4.shared.b16 {%0,%1,%2,%3}, [%4];"
                 : "=r"(r[0]), "=r"(r[1]), "=r"(r[2]), "=r"(r[3]) : "r"(a));
}
// m16n8k32 e4m3 x e4m3 -> f32 (fragment layout == fp16 k16 with 2 fp8/lane-elem)
__device__ __forceinline__ void mma_fp8(float* d, const uint32_t* a, uint32_t b0, uint32_t b1) {
    asm volatile(
        "mma.sync.aligned.m16n8k32.row.col.f32.e4m3.e4m3.f32 "
        "{%0,%1,%2,%3}, {%4,%5,%6,%7}, {%8,%9}, {%0,%1,%2,%3};"
        : "+f"(d[0]), "+f"(d[1]), "+f"(d[2]), "+f"(d[3])
        : "r"(a[0]), "r"(a[1]), "r"(a[2]), "r"(a[3]), "r"(b0), "r"(b1));
}

// ------------------------------ aux kernels --------------------------------
__global__ void detect_kernel(const unsigned* __restrict__ w) {
    int ok = 1;
    for (int i = threadIdx.x; i < 256; i += 32)
        if (w[i] & 0x000FFFFFu) ok = 0;
    ok = __all_sync(0xffffffffu, ok) ? 1 : 0;
    if (threadIdx.x == 0) g_flag = ok;
}

// normalize weights to contiguous e4m3 bytes
__global__ void norm_w_kernel(const void* __restrict__ w, uint8_t* __restrict__ out, size_t n4) {
    size_t i = (size_t)blockIdx.x * blockDim.x + threadIdx.x;
    if (i >= n4) return;
    if (g_flag) {
        float4 v = reinterpret_cast<const float4*>(w)[i];
        uchar4 o;
        o.x = __nv_fp8_e4m3(v.x).__x; o.y = __nv_fp8_e4m3(v.y).__x;
        o.z = __nv_fp8_e4m3(v.z).__x; o.w = __nv_fp8_e4m3(v.w).__x;
        reinterpret_cast<uchar4*>(out)[i] = o;
    } else {
        reinterpret_cast<uchar4*>(out)[i] = reinterpret_cast<const uchar4*>(w)[i];
    }
}

// x -> e4m3 bytes + scales. One warp per (row, 128-col group).
__global__ void fq_x_kernel(const float* __restrict__ x, uint8_t* __restrict__ q,
                            float* __restrict__ sc, int cols) {
    int warp = (blockIdx.x * blockDim.x + threadIdx.x) >> 5;
    int lane = threadIdx.x & 31;
    int ng = cols / QB;
    int row = warp / ng, grp = warp % ng;
    size_t off = (size_t)row * cols + grp * QB;
    float4 v = reinterpret_cast<const float4*>(x + off)[lane];
    float amax = fmaxf(fmaxf(fabsf(v.x), fabsf(v.y)), fmaxf(fabsf(v.z), fabsf(v.w)));
#pragma unroll
    for (int o = 16; o; o >>= 1)
        amax = fmaxf(amax, __shfl_xor_sync(0xffffffffu, amax, o));
    float scale = fmaxf(amax / FP8_MAX, 1e-12f);
    uchar4 u;
    u.x = __nv_fp8_e4m3(fminf(fmaxf(v.x / scale, -FP8_MAX), FP8_MAX)).__x;
    u.y = __nv_fp8_e4m3(fminf(fmaxf(v.y / scale, -FP8_MAX), FP8_MAX)).__x;
    u.z = __nv_fp8_e4m3(fminf(fmaxf(v.z / scale, -FP8_MAX), FP8_MAX)).__x;
    u.w = __nv_fp8_e4m3(fminf(fmaxf(v.w / scale, -FP8_MAX), FP8_MAX)).__x;
    reinterpret_cast<uchar4*>(q + off)[lane] = u;
    if (lane == 0) sc[(size_t)row * ng + grp] = scale;
}

__global__ void combine_fq_kernel(const float* __restrict__ gate, const float* __restrict__ up,
                                  uint8_t* __restrict__ q, float* __restrict__ sc, int cols) {
    int warp = (blockIdx.x * blockDim.x + threadIdx.x) >> 5;
    int lane = threadIdx.x & 31;
    int ng = cols / QB;
    int row = warp / ng, grp = warp % ng;
    size_t off = (size_t)row * cols + grp * QB;
    float4 g = reinterpret_cast<const float4*>(gate + off)[lane];
    float4 u = reinterpret_cast<const float4*>(up + off)[lane];
    float h[4];
    h[0] = g.x * (1.0f / (1.0f + expf(-g.x))) * u.x;
    h[1] = g.y * (1.0f / (1.0f + expf(-g.y))) * u.y;
    h[2] = g.z * (1.0f / (1.0f + expf(-g.z))) * u.z;
    h[3] = g.w * (1.0f / (1.0f + expf(-g.w))) * u.w;
    float amax = fmaxf(fmaxf(fabsf(h[0]), fabsf(h[1])), fmaxf(fabsf(h[2]), fabsf(h[3])));
#pragma unroll
    for (int o = 16; o; o >>= 1)
        amax = fmaxf(amax, __shfl_xor_sync(0xffffffffu, amax, o));
    float scale = fmaxf(amax / FP8_MAX, 1e-12f);
    uchar4 o4;
    o4.x = __nv_fp8_e4m3(fminf(fmaxf(h[0] / scale, -FP8_MAX), FP8_MAX)).__x;
    o4.y = __nv_fp8_e4m3(fminf(fmaxf(h[1] / scale, -FP8_MAX), FP8_MAX)).__x;
    o4.z = __nv_fp8_e4m3(fminf(fmaxf(h[2] / scale, -FP8_MAX), FP8_MAX)).__x;
    o4.w = __nv_fp8_e4m3(fminf(fmaxf(h[3] / scale, -FP8_MAX), FP8_MAX)).__x;
    reinterpret_cast<uchar4*>(q + off)[lane] = o4;
    if (lane == 0) sc[(size_t)row * ng + grp] = scale;
}

// --------------------------- main GEMM kernel ------------------------------
// C[bm:+128, bn:+128] = sum_kb sA[m,kb]*sW[nb,kb] * (A128 @ B128^T), fp8 MMA.
// 16 warps, 32x32 warp tiles, 4-stage cp.async pipeline, chunk = 128 K bytes.
__global__ void __launch_bounds__(512, 1) gemm_fp8_kernel(
    const uint8_t* __restrict__ A, const uint8_t* __restrict__ B,
    const float* __restrict__ Asc, const float* __restrict__ Wsc,
    float* __restrict__ C, int N, int K)
{
    extern __shared__ char smem[];
    const uint32_t sb = smem_u32(smem);
    const int tid = threadIdx.x, lane = tid & 31, wid = tid >> 5;
    const int wm = wid >> 2, wn = wid & 3;            // 4x4 warp grid
    const int bm = blockIdx.x * 128, bn = blockIdx.y * 128;
    const int nch = K >> 7;

    // ---- stage loader: 128x128 fp8 A and B tiles, 16B chunks, XOR swizzle --
    auto load_stage = [&](int s, int c) {
        const uint32_t base = sb + (uint32_t)s * STAGE_B;
#pragma unroll
        for (int i = 0; i < 2; i++) {
            int idx = tid + (i << 9);                 // 0..1023
            int row = idx >> 3, ch = idx & 7;
            uint32_t dst = base + (uint32_t)(row << 7) + (uint32_t)((ch ^ (row & 7)) << 4);
            cp16(dst, A + (size_t)(bm + row) * K + c * 128 + ch * 16);
        }
#pragma unroll
        for (int i = 0; i < 2; i++) {
            int idx = tid + (i << 9);
            int row = idx >> 3, ch = idx & 7;
            uint32_t dst = base + 16384u + (uint32_t)(row << 7) + (uint32_t)((ch ^ (row & 7)) << 4);
            cp16(dst, B + (size_t)(bn + row) * K + c * 128 + ch * 16);
        }
        asm volatile("cp.async.commit_group;");
    };

    float full[2][4][4];
#pragma unroll
    for (int t = 0; t < 2; t++)
#pragma unroll
        for (int j = 0; j < 4; j++)
#pragma unroll
            for (int r = 0; r < 4; r++) full[t][j][r] = 0.0f;

    for (int c = 0; c < STAGES - 1; c++) load_stage(c, c);

    const float* wsc = Wsc + (size_t)blockIdx.y * nch;

    for (int c = 0; c < nch; c++) {
        asm volatile("cp.async.wait_group %0;" :: "n"(STAGES - 2));
        __syncthreads();

        // prefetch promotion scales for this chunk (hidden under MMA loop)
        float sA[2][2];
#pragma unroll
        for (int t = 0; t < 2; t++)
#pragma unroll
            for (int h = 0; h < 2; h++) {
                int row = bm + wm * 32 + t * 16 + h * 8 + (lane >> 2);
                sA[t][h] = __ldg(&Asc[(size_t)row * nch + c]);
            }
        const float sw = __ldg(&wsc[c]);

        {   // issue next chunk into the stage freed last iteration
            int cl = c + STAGES - 1;
            if (cl < nch) load_stage(cl % STAGES, cl);
            else asm volatile("cp.async.commit_group;");
        }

        const uint32_t Ab = sb + (uint32_t)(c % STAGES) * STAGE_B;
        const uint32_t Bb = Ab + 16384u;

        float cacc[2][4][4];
#pragma unroll
        for (int t = 0; t < 2; t++)
#pragma unroll
            for (int j = 0; j < 4; j++)
#pragma unroll
                for (int r = 0; r < 4; r++) cacc[t][j][r] = 0.0f;

#pragma unroll
        for (int ks = 0; ks < 4; ks++) {                 // 4 x k32 = 128 K
            uint32_t a[2][4], b[2][4];
#pragma unroll
            for (int t = 0; t < 2; t++) {
                int mrow = wm * 32 + t * 16 + (lane & 15);
                int chn = ((ks << 1) + (lane >> 4)) ^ (mrow & 7);   // 16B unit
                ldsm4(a[t], Ab + (uint32_t)(mrow << 7) + (uint32_t)(chn << 4));
            }
#pragma unroll
            for (int p = 0; p < 2; p++) {
                int nrow = wn * 32 + p * 16 + (lane & 15);
                int chn = ((ks << 1) + (lane >> 4)) ^ (nrow & 7);
                ldsm4(b[p], Bb + (uint32_t)(nrow << 7) + (uint32_t)(chn << 4));
            }
#pragma unroll
            for (int t = 0; t < 2; t++)
#pragma unroll
                for (int j = 0; j < 4; j++) {
                    int p = j >> 1, o = j & 1;
                    mma_fp8(cacc[t][j], a[t], b[p][o], b[p][o + 2]);
                }
        }

        // promote this 128-K block with exact fp32 scales
#pragma unroll
        for (int t = 0; t < 2; t++)
#pragma unroll
            for (int h = 0; h < 2; h++) {
                float s = sA[t][h] * sw;
#pragma unroll
                for (int j = 0; j < 4; j++) {
                    full[t][j][2 * h]     = fmaf(s, cacc[t][j][2 * h],     full[t][j][2 * h]);
                    full[t][j][2 * h + 1] = fmaf(s, cacc[t][j][2 * h + 1], full[t][j][2 * h + 1]);
                }
            }
        __syncthreads();
    }

    // epilogue
#pragma unroll
    for (int t = 0; t < 2; t++)
#pragma unroll
        for (int h = 0; h < 2; h++) {
            int row = bm + wm * 32 + t * 16 + h * 8 + (lane >> 2);
#pragma unroll
            for (int j = 0; j < 4; j++) {
                int col = bn + wn * 32 + j * 8 + (lane & 3) * 2;
                float2 v = make_float2(full[t][j][2 * h], full[t][j][2 * h + 1]);
                *reinterpret_cast<float2*>(C + (size_t)row * N + col) = v;
            }
        }
}

}  // namespace

// ============================================================================
extern "C" void kernel_launch(void* const* d_in, const int* in_sizes, int n_in,
                              void* d_out, int out_size) {
    const float* x  = (const float*)d_in[0];
    const void*  gw = d_in[1];
    const float* gs = (const float*)d_in[2];
    const void*  uw = d_in[3];
    const float* us = (const float*)d_in[4];
    const void*  dw = d_in[5];
    const float* ds = (const float*)d_in[6];
    float* out = (float*)d_out;

    uint8_t *xq, *gwq, *uwq, *dwq, *hq;
    float *xs, *gate, *up, *hs;
    cudaGetSymbolAddress((void**)&xq,  g_xq);
    cudaGetSymbolAddress((void**)&xs,  g_xs);
    cudaGetSymbolAddress((void**)&gwq, g_gw);
    cudaGetSymbolAddress((void**)&uwq, g_uw);
    cudaGetSymbolAddress((void**)&dwq, g_dw);
    cudaGetSymbolAddress((void**)&gate, g_gate);
    cudaGetSymbolAddress((void**)&up,   g_up);
    cudaGetSymbolAddress((void**)&hq,  g_hq);
    cudaGetSymbolAddress((void**)&hs,  g_hs);

    cudaFuncSetAttribute(gemm_fp8_kernel, cudaFuncAttributeMaxDynamicSharedMemorySize, SMEM_SZ);

    detect_kernel<<<1, 32>>>((const unsigned*)gw);

    {   // weights -> contiguous e4m3 bytes
        size_t n4 = (size_t)II * HH / 4;
        int blocks = (int)((n4 + 255) / 256);
        norm_w_kernel<<<blocks, 256>>>(gw, gwq, n4);
        norm_w_kernel<<<blocks, 256>>>(uw, uwq, n4);
        norm_w_kernel<<<blocks, 256>>>(dw, dwq, n4);
    }

    fq_x_kernel<<<MM * (HH / QB) / 8, 256>>>(x, xq, xs, HH);

    gemm_fp8_kernel<<<dim3(MM / 128, II / 128), 512, SMEM_SZ>>>(xq, gwq, xs, gs, gate, II, HH);
    gemm_fp8_kernel<<<dim3(MM / 128, II / 128), 512, SMEM_SZ>>>(xq, uwq, xs, us, up,   II, HH);

    combine_fq_kernel<<<MM * (II / QB) / 8, 256>>>(gate, up, hq, hs, II);

    gemm_fp8_kernel<<<dim3(MM / 128, HH / 128), 512, SMEM_SZ>>>(hq, dwq, hs, ds, out, HH, II);
}

// round 5
// speedup vs baseline: 1.0291x; 1.0291x over previous
#include <cuda_runtime.h>
#include <cuda_fp8.h>
#include <cuda_fp16.h>
#include <cstdint>

// ============================================================================
// FineGrainedFP8SwiGLUMLP — Round 4: fp16 HMMA core (legacy-ceiling-bound)
// consuming raw e4m3 bytes with in-kernel cvt.e4m3x2->f16x2 expansion,
// SwiGLU+fake-quant fused into the up-GEMM epilogue.
//
//   detect   : classify fp8-weight storage (raw e4m3 bytes vs fp32)
//   norm_w   : only if fp32-stored: weights -> e4m3 bytes (early-exit else)
//   fq_x     : x -> e4m3 bytes + per-(row,128grp) fp32 scale (bit-exact)
//   gemm     : C = Aq @ Bq^T, fp16 MMA per 128-K block, fp32 promotion;
//              optional fused epilogue: h=silu(gate)*up -> e4m3 + scales
// ============================================================================

namespace {

constexpr int MM = 4096, HH = 4096, II = 14336, QB = 128;
constexpr float FP8_MAX = 448.0f;
constexpr int FP8_STAGES = 3;
constexpr int STAGE_B = 32768;                       // 16KB A + 16KB B fp8
constexpr int BUF_B   = 65536;                       // 32KB A + 32KB B fp16
constexpr int SMEM_SZ = FP8_STAGES * STAGE_B + 2 * BUF_B;   // 96 + 128 = 224KB

// ------------------------------- scratch -----------------------------------
__device__ int     g_flag;
__device__ uint8_t g_xq[(size_t)MM * HH];
__device__ float   g_xs[(size_t)MM * (HH / QB)];
__device__ uint8_t g_gw[(size_t)II * HH];
__device__ uint8_t g_uw[(size_t)II * HH];
__device__ uint8_t g_dw[(size_t)HH * II];
__device__ float   g_gate[(size_t)MM * II];
__device__ uint8_t g_hq[(size_t)MM * II];
__device__ float   g_hs[(size_t)MM * (II / QB)];

// --------------------------- PTX helpers -----------------------------------
__device__ __forceinline__ uint32_t smem_u32(const void* p) {
    uint32_t a;
    asm("{ .reg .u64 t; cvta.to.shared.u64 t, %1; cvt.u32.u64 %0, t; }" : "=r"(a) : "l"(p));
    return a;
}
__device__ __forceinline__ void cp16(uint32_t dst, const void* src) {
    asm volatile("cp.async.cg.shared.global [%0], [%1], 16;" :: "r"(dst), "l"(src));
}
__device__ __forceinline__ void ldsm4(uint32_t* r, uint32_t a) {
    asm volatile("ldmatrix.sync.aligned.m8n8.x4.shared.b16 {%0,%1,%2,%3}, [%4];"
                 : "=r"(r[0]), "=r"(r[1]), "=r"(r[2]), "=r"(r[3]) : "r"(a));
}
__device__ __forceinline__ void mma_f16(float* d, const uint32_t* a, uint32_t b0, uint32_t b1) {
    asm volatile(
        "mma.sync.aligned.m16n8k16.row.col.f32.f16.f16.f32 "
        "{%0,%1,%2,%3}, {%4,%5,%6,%7}, {%8,%9}, {%0,%1,%2,%3};"
        : "+f"(d[0]), "+f"(d[1]), "+f"(d[2]), "+f"(d[3])
        : "r"(a[0]), "r"(a[1]), "r"(a[2]), "r"(a[3]), "r"(b0), "r"(b1));
}
// 2x e4m3 -> 2x fp16, exact
__device__ __forceinline__ uint32_t cvt_f8x2(uint32_t packed) {
    uint32_t r;
    asm("{ .reg .b16 h; cvt.u16.u32 h, %1; cvt.rn.f16x2.e4m3x2 %0, h; }"
        : "=r"(r) : "r"(packed));
    return r;
}
__device__ __forceinline__ void lds128(uint4& v, uint32_t a) {
    asm volatile("ld.shared.v4.u32 {%0,%1,%2,%3}, [%4];"
                 : "=r"(v.x), "=r"(v.y), "=r"(v.z), "=r"(v.w) : "r"(a));
}
__device__ __forceinline__ void sts128(uint32_t a, uint32_t r0, uint32_t r1, uint32_t r2, uint32_t r3) {
    asm volatile("st.shared.v4.u32 [%0], {%1,%2,%3,%4};"
                 :: "r"(a), "r"(r0), "r"(r1), "r"(r2), "r"(r3));
}

// ------------------------------ aux kernels --------------------------------
__global__ void detect_kernel(const unsigned* __restrict__ w) {
    int ok = 1;
    for (int i = threadIdx.x; i < 256; i += 32)
        if (w[i] & 0x000FFFFFu) ok = 0;
    ok = __all_sync(0xffffffffu, ok) ? 1 : 0;
    if (threadIdx.x == 0) g_flag = ok;
}

// only if fp32-stored: compress to e4m3 bytes (grid-stride; early exit on flag=0)
__global__ void norm_w_kernel(const float* __restrict__ w, uint8_t* __restrict__ out, size_t n4) {
    if (!g_flag) return;
    for (size_t i = (size_t)blockIdx.x * blockDim.x + threadIdx.x; i < n4;
         i += (size_t)gridDim.x * blockDim.x) {
        float4 v = reinterpret_cast<const float4*>(w)[i];
        uchar4 o;
        o.x = __nv_fp8_e4m3(v.x).__x; o.y = __nv_fp8_e4m3(v.y).__x;
        o.z = __nv_fp8_e4m3(v.z).__x; o.w = __nv_fp8_e4m3(v.w).__x;
        reinterpret_cast<uchar4*>(out)[i] = o;
    }
}

// x -> e4m3 bytes + scales. One warp per (row, 128-col group).
__global__ void fq_x_kernel(const float* __restrict__ x, uint8_t* __restrict__ q,
                            float* __restrict__ sc, int cols) {
    int warp = (blockIdx.x * blockDim.x + threadIdx.x) >> 5;
    int lane = threadIdx.x & 31;
    int ng = cols / QB;
    int row = warp / ng, grp = warp % ng;
    size_t off = (size_t)row * cols + grp * QB;
    float4 v = reinterpret_cast<const float4*>(x + off)[lane];
    float amax = fmaxf(fmaxf(fabsf(v.x), fabsf(v.y)), fmaxf(fabsf(v.z), fabsf(v.w)));
#pragma unroll
    for (int o = 16; o; o >>= 1)
        amax = fmaxf(amax, __shfl_xor_sync(0xffffffffu, amax, o));
    float scale = fmaxf(amax / FP8_MAX, 1e-12f);
    uchar4 u;
    u.x = __nv_fp8_e4m3(fminf(fmaxf(v.x / scale, -FP8_MAX), FP8_MAX)).__x;
    u.y = __nv_fp8_e4m3(fminf(fmaxf(v.y / scale, -FP8_MAX), FP8_MAX)).__x;
    u.z = __nv_fp8_e4m3(fminf(fmaxf(v.z / scale, -FP8_MAX), FP8_MAX)).__x;
    u.w = __nv_fp8_e4m3(fminf(fmaxf(v.w / scale, -FP8_MAX), FP8_MAX)).__x;
    reinterpret_cast<uchar4*>(q + off)[lane] = u;
    if (lane == 0) sc[(size_t)row * ng + grp] = scale;
}

// --------------------------- main GEMM kernel ------------------------------
// A: raw e4m3 [M,K]. B: e4m3 weights, pointer chosen by g_flag.
// Per-chunk: cp.async fp8 -> smem stage; interleaved cvt to fp16 double buf;
// fp16 MMA; fp32 promotion with sA[m,kb]*sW[nb,kb].
// Epilogue: fused==0 -> write fp32 C. fused==1 -> h=silu(gate)*u, per-row
// amax over the 128-col tile, e4m3 quantize -> Hq bytes + Hs scales.
__global__ void __launch_bounds__(512, 1) gemm_kernel(
    const uint8_t* __restrict__ A,
    const uint8_t* __restrict__ Braw, const uint8_t* __restrict__ Bnorm,
    const float* __restrict__ Asc, const float* __restrict__ Wsc,
    float* __restrict__ C, const float* __restrict__ GateIn,
    uint8_t* __restrict__ Hq, float* __restrict__ Hs,
    int N, int K, int fused)
{
    extern __shared__ char smem[];
    const uint32_t sb = smem_u32(smem);
    const uint32_t FB = sb + FP8_STAGES * STAGE_B;    // fp16 double buffer
    const int tid = threadIdx.x, lane = tid & 31, wid = tid >> 5;
    const int wm = wid >> 2, wn = wid & 3;
    const int bm = blockIdx.x * 128, bn = blockIdx.y * 128;
    const int nch = K >> 7;
    const uint8_t* B = g_flag ? Bnorm : Braw;

    // ---- fp8 stage loader (16B chunks, XOR swizzle on 16B units) ----------
    auto load_stage = [&](int s, int c) {
        const uint32_t base = sb + (uint32_t)s * STAGE_B;
#pragma unroll
        for (int i = 0; i < 2; i++) {
            int idx = tid + (i << 9);
            int row = idx >> 3, ch = idx & 7;
            uint32_t dst = base + (uint32_t)(row << 7) + (uint32_t)((ch ^ (row & 7)) << 4);
            cp16(dst, A + (size_t)(bm + row) * K + c * 128 + ch * 16);
        }
#pragma unroll
        for (int i = 0; i < 2; i++) {
            int idx = tid + (i << 9);
            int row = idx >> 3, ch = idx & 7;
            uint32_t dst = base + 16384u + (uint32_t)(row << 7) + (uint32_t)((ch ^ (row & 7)) << 4);
            cp16(dst, B + (size_t)(bn + row) * K + c * 128 + ch * 16);
        }
        asm volatile("cp.async.commit_group;");
    };

    // ---- conversion: this thread's role (A half for tid<256, B half else) -
    const int crow = tid & 127;
    const int chalf = (tid >> 7) & 1;
    const uint32_t csrc_off = (tid >= 256) ? 16384u : 0u;
    const uint32_t cdst_off = (tid >= 256) ? 32768u : 0u;
    // convert one 16-elem slice s (0..3) of this thread's 64 elems
    auto convert_slice = [&](uint32_t stage_base, uint32_t buf_base, int s) {
        int ch8 = chalf * 4 + s;
        uint32_t src = stage_base + csrc_off + (uint32_t)(crow << 7)
                     + (uint32_t)((ch8 ^ (crow & 7)) << 4);
        uint4 v; lds128(v, src);
        uint32_t f[8];
        f[0] = cvt_f8x2(v.x);       f[1] = cvt_f8x2(v.x >> 16);
        f[2] = cvt_f8x2(v.y);       f[3] = cvt_f8x2(v.y >> 16);
        f[4] = cvt_f8x2(v.z);       f[5] = cvt_f8x2(v.z >> 16);
        f[6] = cvt_f8x2(v.w);       f[7] = cvt_f8x2(v.w >> 16);
        int ch16 = chalf * 8 + s * 2;
        uint32_t d0 = buf_base + cdst_off + (uint32_t)(crow << 8)
                    + (uint32_t)((ch16 ^ (crow & 7)) << 4);
        uint32_t d1 = buf_base + cdst_off + (uint32_t)(crow << 8)
                    + (uint32_t)(((ch16 + 1) ^ (crow & 7)) << 4);
        sts128(d0, f[0], f[1], f[2], f[3]);
        sts128(d1, f[4], f[5], f[6], f[7]);
    };

    float full[2][4][4];
#pragma unroll
    for (int t = 0; t < 2; t++)
#pragma unroll
        for (int j = 0; j < 4; j++)
#pragma unroll
            for (int r = 0; r < 4; r++) full[t][j][r] = 0.0f;

    // ---- prologue ----------------------------------------------------------
    load_stage(0, 0);
    if (1 < nch) load_stage(1, 1);
    if (2 < nch) load_stage(2, 2);
    asm volatile("cp.async.wait_group %0;" :: "n"(2));
    __syncthreads();
#pragma unroll
    for (int s = 0; s < 4; s++) convert_slice(sb, FB, s);   // chunk0 -> buf0

    const float* wsc = Wsc + (size_t)blockIdx.y * nch;
    int pb = 0;

    for (int c = 0; c < nch; c++) {
        __syncthreads();   // conversions(buf[pb]) done; stage (c+1)%3 visible

        // scales for this chunk (LDG hidden under MMA loop)
        float sA[2][2];
#pragma unroll
        for (int t = 0; t < 2; t++)
#pragma unroll
            for (int h = 0; h < 2; h++) {
                int row = bm + wm * 32 + t * 16 + h * 8 + (lane >> 2);
                sA[t][h] = __ldg(&Asc[(size_t)row * nch + c]);
            }
        const float sw = __ldg(&wsc[c]);

        if (c + 3 < nch) load_stage(c % FP8_STAGES, c + 3);
        asm volatile("cp.async.wait_group %0;" :: "n"(2));

        const uint32_t Ab = FB + (uint32_t)pb * BUF_B;
        const uint32_t Bb = Ab + 32768u;
        const uint32_t nstage = sb + (uint32_t)((c + 1) % FP8_STAGES) * STAGE_B;
        const uint32_t nbuf = FB + (uint32_t)(pb ^ 1) * BUF_B;
        const bool do_cvt = (c + 1 < nch);

        float cacc[2][4][4];
#pragma unroll
        for (int t = 0; t < 2; t++)
#pragma unroll
            for (int j = 0; j < 4; j++)
#pragma unroll
                for (int r = 0; r < 4; r++) cacc[t][j][r] = 0.0f;

#pragma unroll
        for (int ks = 0; ks < 8; ks++) {
            uint32_t a[2][4], b[2][4];
#pragma unroll
            for (int t = 0; t < 2; t++) {
                int mrow = wm * 32 + t * 16 + (lane & 15);
                int chn = ((ks << 1) + (lane >> 4)) ^ (mrow & 7);
                ldsm4(a[t], Ab + (uint32_t)(mrow << 8) + (uint32_t)(chn << 4));
            }
#pragma unroll
            for (int p = 0; p < 2; p++) {
                int nrow = wn * 32 + p * 16 + (lane & 15);
                int chn = ((ks << 1) + (lane >> 4)) ^ (nrow & 7);
                ldsm4(b[p], Bb + (uint32_t)(nrow << 8) + (uint32_t)(chn << 4));
            }
            if (do_cvt && !(ks & 1)) convert_slice(nstage, nbuf, ks >> 1);
#pragma unroll
            for (int t = 0; t < 2; t++)
#pragma unroll
                for (int j = 0; j < 4; j++) {
                    int p = j >> 1, o = j & 1;
                    mma_f16(cacc[t][j], a[t], b[p][o], b[p][o + 2]);
                }
        }

        // promote this 128-K block with exact fp32 scales
#pragma unroll
        for (int t = 0; t < 2; t++)
#pragma unroll
            for (int h = 0; h < 2; h++) {
                float s = sA[t][h] * sw;
#pragma unroll
                for (int j = 0; j < 4; j++) {
                    full[t][j][2 * h]     = fmaf(s, cacc[t][j][2 * h],     full[t][j][2 * h]);
                    full[t][j][2 * h + 1] = fmaf(s, cacc[t][j][2 * h + 1], full[t][j][2 * h + 1]);
                }
            }
        pb ^= 1;
    }

    if (!fused) {
        // plain fp32 epilogue
#pragma unroll
        for (int t = 0; t < 2; t++)
#pragma unroll
            for (int h = 0; h < 2; h++) {
                int row = bm + wm * 32 + t * 16 + h * 8 + (lane >> 2);
#pragma unroll
                for (int j = 0; j < 4; j++) {
                    int col = bn + wn * 32 + j * 8 + (lane & 3) * 2;
                    *reinterpret_cast<float2*>(C + (size_t)row * N + col) =
                        make_float2(full[t][j][2 * h], full[t][j][2 * h + 1]);
                }
            }
        return;
    }

    // ---- fused SwiGLU + fake-quant epilogue --------------------------------
    // full[] currently holds up_out. h = silu(gate)*up; overwrite full with h.
    __syncthreads();
    int* smax = reinterpret_cast<int*>(smem);          // 128 per-row amax
    if (tid < 128) smax[tid] = 0;
    __syncthreads();

#pragma unroll
    for (int t = 0; t < 2; t++)
#pragma unroll
        for (int h = 0; h < 2; h++) {
            int rl = wm * 32 + t * 16 + h * 8 + (lane >> 2);
            int row = bm + rl;
            float lm = 0.0f;
#pragma unroll
            for (int j = 0; j < 4; j++) {
                int col = bn + wn * 32 + j * 8 + (lane & 3) * 2;
                float2 g = *reinterpret_cast<const float2*>(GateIn + (size_t)row * N + col);
                float h0 = g.x * (1.0f / (1.0f + expf(-g.x))) * full[t][j][2 * h];
                float h1 = g.y * (1.0f / (1.0f + expf(-g.y))) * full[t][j][2 * h + 1];
                full[t][j][2 * h] = h0;
                full[t][j][2 * h + 1] = h1;
                lm = fmaxf(lm, fmaxf(fabsf(h0), fabsf(h1)));
            }
            atomicMax(&smax[rl], __float_as_int(lm));
        }
    __syncthreads();

#pragma unroll
    for (int t = 0; t < 2; t++)
#pragma unroll
        for (int h = 0; h < 2; h++) {
            int rl = wm * 32 + t * 16 + h * 8 + (lane >> 2);
            int row = bm + rl;
            float amax = __int_as_float(smax[rl]);
            float scale = fmaxf(amax / FP8_MAX, 1e-12f);
#pragma unroll
            for (int j = 0; j < 4; j++) {
                int col = bn + wn * 32 + j * 8 + (lane & 3) * 2;
                uint8_t q0 = __nv_fp8_e4m3(
                    fminf(fmaxf(full[t][j][2 * h] / scale, -FP8_MAX), FP8_MAX)).__x;
                uint8_t q1 = __nv_fp8_e4m3(
                    fminf(fmaxf(full[t][j][2 * h + 1] / scale, -FP8_MAX), FP8_MAX)).__x;
                *reinterpret_cast<uint16_t*>(Hq + (size_t)row * N + col) =
                    (uint16_t)q0 | ((uint16_t)q1 << 8);
            }
            if (wn == 0 && (lane & 3) == 0)
                Hs[(size_t)row * (N / QB) + blockIdx.y] = scale;
        }
}

}  // namespace

// ============================================================================
extern "C" void kernel_launch(void* const* d_in, const int* in_sizes, int n_in,
                              void* d_out, int out_size) {
    const float* x  = (const float*)d_in[0];
    const uint8_t* gw = (const uint8_t*)d_in[1];
    const float* gs = (const float*)d_in[2];
    const uint8_t* uw = (const uint8_t*)d_in[3];
    const float* us = (const float*)d_in[4];
    const uint8_t* dw = (const uint8_t*)d_in[5];
    const float* ds = (const float*)d_in[6];
    float* out = (float*)d_out;

    uint8_t *xq, *gwq, *uwq, *dwq, *hq;
    float *xs, *gate, *hs;
    cudaGetSymbolAddress((void**)&xq,  g_xq);
    cudaGetSymbolAddress((void**)&xs,  g_xs);
    cudaGetSymbolAddress((void**)&gwq, g_gw);
    cudaGetSymbolAddress((void**)&uwq, g_uw);
    cudaGetSymbolAddress((void**)&dwq, g_dw);
    cudaGetSymbolAddress((void**)&gate, g_gate);
    cudaGetSymbolAddress((void**)&hq,  g_hq);
    cudaGetSymbolAddress((void**)&hs,  g_hs);

    cudaFuncSetAttribute(gemm_kernel, cudaFuncAttributeMaxDynamicSharedMemorySize, SMEM_SZ);

    detect_kernel<<<1, 32>>>((const unsigned*)gw);

    {   // only active when weights arrive as fp32 (g_flag==1)
        size_t n4 = (size_t)II * HH / 4;
        norm_w_kernel<<<2048, 256>>>((const float*)gw, gwq, n4);
        norm_w_kernel<<<2048, 256>>>((const float*)uw, uwq, n4);
        norm_w_kernel<<<2048, 256>>>((const float*)dw, dwq, n4);
    }

    fq_x_kernel<<<MM * (HH / QB) / 8, 256>>>(x, xq, xs, HH);

    // gate GEMM -> fp32 gate buffer
    gemm_kernel<<<dim3(MM / 128, II / 128), 512, SMEM_SZ>>>(
        xq, gw, gwq, xs, gs, gate, nullptr, nullptr, nullptr, II, HH, 0);
    // up GEMM with fused swiglu+quant -> hq/hs
    gemm_kernel<<<dim3(MM / 128, II / 128), 512, SMEM_SZ>>>(
        xq, uw, uwq, xs, us, nullptr, gate, hq, hs, II, HH, 1);
    // down GEMM -> fp32 out
    gemm_kernel<<<dim3(MM / 128, HH / 128), 512, SMEM_SZ>>>(
        hq, dw, dwq, hs, ds, out, nullptr, nullptr, nullptr, HH, II, 0);
}

// round 6
// speedup vs baseline: 1.0355x; 1.0062x over previous
#include <cuda_runtime.h>
#include <cuda_fp8.h>
#include <cuda_bf16.h>
#include <cstdint>

// ============================================================================
// FineGrainedFP8SwiGLUMLP — Round 5: R2 bf16 HMMA core (at legacy tensor-pipe
// ceiling, do not touch) + SwiGLU/fake-quant fused into the up-GEMM epilogue.
//
//   detect      : classify fp8-weight storage (fp32-stored confirmed, keep both)
//   convert_w   : weights -> exact bf16
//   fq_x        : x -> bf16-quantized values + per-(row,128grp) fp32 scale
//   gemm_bf16   : C = Aq @ Bq^T, MMA per 128-K block, promote with sA*sW;
//                 fused==1: epilogue h=silu(gate)*up -> e4m3->bf16 + scales
// ============================================================================

namespace {

constexpr int MM = 4096, HH = 4096, II = 14336, QB = 128;
constexpr float FP8_MAX = 448.0f;
constexpr int STAGES = 3;
constexpr int STAGE_B = 65536;                    // 32KB A + 32KB B (bf16 128x128)
constexpr int SMEM_SZ = STAGES * STAGE_B;         // 192 KB

// ------------------------------- scratch -----------------------------------
__device__ int           g_flag;
__device__ __nv_bfloat16 g_xb[(size_t)MM * HH];
__device__ float         g_xs[(size_t)MM * (HH / QB)];
__device__ __nv_bfloat16 g_gw[(size_t)II * HH];
__device__ __nv_bfloat16 g_uw[(size_t)II * HH];
__device__ __nv_bfloat16 g_dw[(size_t)HH * II];
__device__ float         g_gate[(size_t)MM * II];
__device__ __nv_bfloat16 g_hb[(size_t)MM * II];
__device__ float         g_hs[(size_t)MM * (II / QB)];

// --------------------------- PTX helpers -----------------------------------
__device__ __forceinline__ uint32_t smem_u32(const void* p) {
    uint32_t a;
    asm("{ .reg .u64 t; cvta.to.shared.u64 t, %1; cvt.u32.u64 %0, t; }" : "=r"(a) : "l"(p));
    return a;
}
__device__ __forceinline__ void cp16(uint32_t dst, const void* src) {
    asm volatile("cp.async.cg.shared.global [%0], [%1], 16;" :: "r"(dst), "l"(src));
}
__device__ __forceinline__ void ldsm4(uint32_t* r, uint32_t a) {
    asm volatile("ldmatrix.sync.aligned.m8n8.x4.shared.b16 {%0,%1,%2,%3}, [%4];"
                 : "=r"(r[0]), "=r"(r[1]), "=r"(r[2]), "=r"(r[3]) : "r"(a));
}
__device__ __forceinline__ void mma_bf16(float* d, const uint32_t* a, uint32_t b0, uint32_t b1) {
    asm volatile(
        "mma.sync.aligned.m16n8k16.row.col.f32.bf16.bf16.f32 "
        "{%0,%1,%2,%3}, {%4,%5,%6,%7}, {%8,%9}, {%0,%1,%2,%3};"
        : "+f"(d[0]), "+f"(d[1]), "+f"(d[2]), "+f"(d[3])
        : "r"(a[0]), "r"(a[1]), "r"(a[2]), "r"(a[3]), "r"(b0), "r"(b1));
}
__device__ __forceinline__ __nv_bfloat16 f8_to_bf16(uint8_t bits) {
    __nv_fp8_e4m3 v; v.__x = bits;
    return __float2bfloat16(float(v));
}

// ------------------------------ aux kernels --------------------------------
__global__ void detect_kernel(const unsigned* __restrict__ w) {
    int ok = 1;
    for (int i = threadIdx.x; i < 256; i += 32)
        if (w[i] & 0x000FFFFFu) ok = 0;
    ok = __all_sync(0xffffffffu, ok) ? 1 : 0;
    if (threadIdx.x == 0) g_flag = ok;
}

__global__ void convert_w_kernel(const void* __restrict__ w, __nv_bfloat16* __restrict__ out,
                                 size_t n4) {
    for (size_t i = (size_t)blockIdx.x * blockDim.x + threadIdx.x; i < n4;
         i += (size_t)gridDim.x * blockDim.x) {
        __nv_bfloat16 o[4];
        if (g_flag) {
            float4 v = reinterpret_cast<const float4*>(w)[i];
            o[0] = __float2bfloat16(float(__nv_fp8_e4m3(v.x)));
            o[1] = __float2bfloat16(float(__nv_fp8_e4m3(v.y)));
            o[2] = __float2bfloat16(float(__nv_fp8_e4m3(v.z)));
            o[3] = __float2bfloat16(float(__nv_fp8_e4m3(v.w)));
        } else {
            uchar4 v = reinterpret_cast<const uchar4*>(w)[i];
            o[0] = f8_to_bf16(v.x); o[1] = f8_to_bf16(v.y);
            o[2] = f8_to_bf16(v.z); o[3] = f8_to_bf16(v.w);
        }
        reinterpret_cast<uint2*>(out)[i] = *reinterpret_cast<uint2*>(o);
    }
}

// x -> bf16 quantized values + scales. One warp per (row, 128-col group).
__global__ void fq_x_kernel(const float* __restrict__ x, __nv_bfloat16* __restrict__ q,
                            float* __restrict__ sc, int cols) {
    int warp = (blockIdx.x * blockDim.x + threadIdx.x) >> 5;
    int lane = threadIdx.x & 31;
    int ng = cols / QB;
    int row = warp / ng, grp = warp % ng;
    size_t off = (size_t)row * cols + grp * QB;
    float4 v = reinterpret_cast<const float4*>(x + off)[lane];
    float amax = fmaxf(fmaxf(fabsf(v.x), fabsf(v.y)), fmaxf(fabsf(v.z), fabsf(v.w)));
#pragma unroll
    for (int o = 16; o; o >>= 1)
        amax = fmaxf(amax, __shfl_xor_sync(0xffffffffu, amax, o));
    float scale = fmaxf(amax / FP8_MAX, 1e-12f);
    __nv_bfloat16 u[4];
    u[0] = __float2bfloat16(float(__nv_fp8_e4m3(fminf(fmaxf(v.x / scale, -FP8_MAX), FP8_MAX))));
    u[1] = __float2bfloat16(float(__nv_fp8_e4m3(fminf(fmaxf(v.y / scale, -FP8_MAX), FP8_MAX))));
    u[2] = __float2bfloat16(float(__nv_fp8_e4m3(fminf(fmaxf(v.z / scale, -FP8_MAX), FP8_MAX))));
    u[3] = __float2bfloat16(float(__nv_fp8_e4m3(fminf(fmaxf(v.w / scale, -FP8_MAX), FP8_MAX))));
    reinterpret_cast<uint2*>(q + off)[lane] = *reinterpret_cast<uint2*>(u);
    if (lane == 0) sc[(size_t)row * ng + grp] = scale;
}

// --------------------------- main GEMM kernel ------------------------------
// 16 warps, 32x32 warp tiles, 3-stage cp.async pipeline, chunk = 128 K.
// fused==0: write fp32 C.  fused==1: h=silu(GateIn)*acc, per-row amax over the
// 128-col tile, e4m3-quantize, store bf16(Hq value) + fp32 scale.
__global__ void __launch_bounds__(512, 1) gemm_bf16_kernel(
    const __nv_bfloat16* __restrict__ A, const __nv_bfloat16* __restrict__ B,
    const float* __restrict__ Asc, const float* __restrict__ Wsc,
    float* __restrict__ C, const float* __restrict__ GateIn,
    __nv_bfloat16* __restrict__ Hb, float* __restrict__ Hs,
    int N, int K, int fused)
{
    extern __shared__ char smem[];
    const uint32_t sb = smem_u32(smem);
    const int tid = threadIdx.x, lane = tid & 31, wid = tid >> 5;
    const int wm = wid >> 2, wn = wid & 3;            // 4x4 warp grid
    const int bm = blockIdx.x * 128, bn = blockIdx.y * 128;
    const int nch = K >> 7;

    auto load_stage = [&](int s, int c) {
        const uint32_t base = sb + (uint32_t)s * STAGE_B;
#pragma unroll
        for (int i = 0; i < 4; i++) {
            int idx = tid + (i << 9);                 // 0..2047
            int row = idx >> 4, ch = idx & 15;
            uint32_t dst = base + (uint32_t)(row << 8) + (uint32_t)((ch ^ (row & 7)) << 4);
            cp16(dst, A + (size_t)(bm + row) * K + c * 128 + ch * 8);
        }
#pragma unroll
        for (int i = 0; i < 4; i++) {
            int idx = tid + (i << 9);
            int row = idx >> 4, ch = idx & 15;
            uint32_t dst = base + 32768u + (uint32_t)(row << 8) + (uint32_t)((ch ^ (row & 7)) << 4);
            cp16(dst, B + (size_t)(bn + row) * K + c * 128 + ch * 8);
        }
        asm volatile("cp.async.commit_group;");
    };

    float full[2][4][4];
#pragma unroll
    for (int t = 0; t < 2; t++)
#pragma unroll
        for (int j = 0; j < 4; j++)
#pragma unroll
            for (int r = 0; r < 4; r++) full[t][j][r] = 0.0f;

    for (int c = 0; c < STAGES - 1; c++) load_stage(c, c);

    const float* wsc = Wsc + (size_t)blockIdx.y * nch;

    for (int c = 0; c < nch; c++) {
        asm volatile("cp.async.wait_group %0;" :: "n"(STAGES - 2));
        __syncthreads();

        // prefetch promotion scales (hidden under the MMA loop)
        float sA[2][2];
#pragma unroll
        for (int t = 0; t < 2; t++)
#pragma unroll
            for (int h = 0; h < 2; h++) {
                int row = bm + wm * 32 + t * 16 + h * 8 + (lane >> 2);
                sA[t][h] = __ldg(&Asc[(size_t)row * nch + c]);
            }
        const float sw = __ldg(&wsc[c]);

        {   // issue next chunk into the stage freed last iteration
            int cl = c + STAGES - 1;
            if (cl < nch) load_stage(cl % STAGES, cl);
            else asm volatile("cp.async.commit_group;");
        }

        const uint32_t Ab = sb + (uint32_t)(c % STAGES) * STAGE_B;
        const uint32_t Bb = Ab + 32768u;

        float cacc[2][4][4];
#pragma unroll
        for (int t = 0; t < 2; t++)
#pragma unroll
            for (int j = 0; j < 4; j++)
#pragma unroll
                for (int r = 0; r < 4; r++) cacc[t][j][r] = 0.0f;

#pragma unroll
        for (int ks = 0; ks < 8; ks++) {
            uint32_t a[2][4], b[2][4];
#pragma unroll
            for (int t = 0; t < 2; t++) {
                int mrow = wm * 32 + t * 16 + (lane & 15);
                int chn = ((ks << 1) + (lane >> 4)) ^ (mrow & 7);
                ldsm4(a[t], Ab + (uint32_t)(mrow << 8) + (uint32_t)(chn << 4));
            }
#pragma unroll
            for (int p = 0; p < 2; p++) {
                int nrow = wn * 32 + p * 16 + (lane & 15);
                int chn = ((ks << 1) + (lane >> 4)) ^ (nrow & 7);
                ldsm4(b[p], Bb + (uint32_t)(nrow << 8) + (uint32_t)(chn << 4));
            }
#pragma unroll
            for (int t = 0; t < 2; t++)
#pragma unroll
                for (int j = 0; j < 4; j++) {
                    int p = j >> 1, o = j & 1;
                    mma_bf16(cacc[t][j], a[t], b[p][o], b[p][o + 2]);
                }
        }

        // promote this 128-K block with exact fp32 scales
#pragma unroll
        for (int t = 0; t < 2; t++)
#pragma unroll
            for (int h = 0; h < 2; h++) {
                float s = sA[t][h] * sw;
#pragma unroll
                for (int j = 0; j < 4; j++) {
                    full[t][j][2 * h]     = fmaf(s, cacc[t][j][2 * h],     full[t][j][2 * h]);
                    full[t][j][2 * h + 1] = fmaf(s, cacc[t][j][2 * h + 1], full[t][j][2 * h + 1]);
                }
            }
        __syncthreads();
    }

    if (!fused) {
#pragma unroll
        for (int t = 0; t < 2; t++)
#pragma unroll
            for (int h = 0; h < 2; h++) {
                int row = bm + wm * 32 + t * 16 + h * 8 + (lane >> 2);
#pragma unroll
                for (int j = 0; j < 4; j++) {
                    int col = bn + wn * 32 + j * 8 + (lane & 3) * 2;
                    *reinterpret_cast<float2*>(C + (size_t)row * N + col) =
                        make_float2(full[t][j][2 * h], full[t][j][2 * h + 1]);
                }
            }
        return;
    }

    // ---- fused SwiGLU + fake-quant epilogue (up GEMM only) -----------------
    int* smax = reinterpret_cast<int*>(smem);          // 128 per-row amax
    if (tid < 128) smax[tid] = 0;
    __syncthreads();

#pragma unroll
    for (int t = 0; t < 2; t++)
#pragma unroll
        for (int h = 0; h < 2; h++) {
            int rl = wm * 32 + t * 16 + h * 8 + (lane >> 2);
            int row = bm + rl;
            float lm = 0.0f;
#pragma unroll
            for (int j = 0; j < 4; j++) {
                int col = bn + wn * 32 + j * 8 + (lane & 3) * 2;
                float2 g = *reinterpret_cast<const float2*>(GateIn + (size_t)row * N + col);
                float h0 = g.x * (1.0f / (1.0f + expf(-g.x))) * full[t][j][2 * h];
                float h1 = g.y * (1.0f / (1.0f + expf(-g.y))) * full[t][j][2 * h + 1];
                full[t][j][2 * h] = h0;
                full[t][j][2 * h + 1] = h1;
                lm = fmaxf(lm, fmaxf(fabsf(h0), fabsf(h1)));
            }
            atomicMax(&smax[rl], __float_as_int(lm));
        }
    __syncthreads();

#pragma unroll
    for (int t = 0; t < 2; t++)
#pragma unroll
        for (int h = 0; h < 2; h++) {
            int rl = wm * 32 + t * 16 + h * 8 + (lane >> 2);
            int row = bm + rl;
            float scale = fmaxf(__int_as_float(smax[rl]) / FP8_MAX, 1e-12f);
#pragma unroll
            for (int j = 0; j < 4; j++) {
                int col = bn + wn * 32 + j * 8 + (lane & 3) * 2;
                __nv_bfloat16 q[2];
                q[0] = __float2bfloat16(float(__nv_fp8_e4m3(
                    fminf(fmaxf(full[t][j][2 * h] / scale, -FP8_MAX), FP8_MAX))));
                q[1] = __float2bfloat16(float(__nv_fp8_e4m3(
                    fminf(fmaxf(full[t][j][2 * h + 1] / scale, -FP8_MAX), FP8_MAX))));
                *reinterpret_cast<uint32_t*>(Hb + (size_t)row * N + col) =
                    *reinterpret_cast<uint32_t*>(q);
            }
            if (wn == 0 && (lane & 3) == 0)
                Hs[(size_t)row * (N / QB) + blockIdx.y] = scale;
        }
}

}  // namespace

// ============================================================================
extern "C" void kernel_launch(void* const* d_in, const int* in_sizes, int n_in,
                              void* d_out, int out_size) {
    const float* x  = (const float*)d_in[0];
    const void*  gw = d_in[1];
    const float* gs = (const float*)d_in[2];
    const void*  uw = d_in[3];
    const float* us = (const float*)d_in[4];
    const void*  dw = d_in[5];
    const float* ds = (const float*)d_in[6];
    float* out = (float*)d_out;

    __nv_bfloat16 *xb, *gwb, *uwb, *dwb, *hb;
    float *xs, *gate, *hs;
    cudaGetSymbolAddress((void**)&xb,  g_xb);
    cudaGetSymbolAddress((void**)&xs,  g_xs);
    cudaGetSymbolAddress((void**)&gwb, g_gw);
    cudaGetSymbolAddress((void**)&uwb, g_uw);
    cudaGetSymbolAddress((void**)&dwb, g_dw);
    cudaGetSymbolAddress((void**)&gate, g_gate);
    cudaGetSymbolAddress((void**)&hb,  g_hb);
    cudaGetSymbolAddress((void**)&hs,  g_hs);

    cudaFuncSetAttribute(gemm_bf16_kernel, cudaFuncAttributeMaxDynamicSharedMemorySize, SMEM_SZ);

    detect_kernel<<<1, 32>>>((const unsigned*)gw);

    {   // weights -> exact bf16
        size_t n4 = (size_t)II * HH / 4;
        convert_w_kernel<<<2048, 256>>>(gw, gwb, n4);
        convert_w_kernel<<<2048, 256>>>(uw, uwb, n4);
        convert_w_kernel<<<2048, 256>>>(dw, dwb, n4);
    }

    fq_x_kernel<<<MM * (HH / QB) / 8, 256>>>(x, xb, xs, HH);

    // gate GEMM -> fp32 gate buffer
    gemm_bf16_kernel<<<dim3(MM / 128, II / 128), 512, SMEM_SZ>>>(
        xb, gwb, xs, gs, gate, nullptr, nullptr, nullptr, II, HH, 0);
    // up GEMM with fused swiglu+fake-quant -> hb/hs
    gemm_bf16_kernel<<<dim3(MM / 128, II / 128), 512, SMEM_SZ>>>(
        xb, uwb, xs, us, nullptr, gate, hb, hs, II, HH, 1);
    // down GEMM -> fp32 out
    gemm_bf16_kernel<<<dim3(MM / 128, HH / 128), 512, SMEM_SZ>>>(
        hb, dwb, hs, ds, out, nullptr, nullptr, nullptr, HH, II, 0);
}

// round 7
// speedup vs baseline: 1.0714x; 1.0347x over previous
#include <cuda_runtime.h>
#include <cuda_fp8.h>
#include <cuda_bf16.h>
#include <cstdint>

// ============================================================================
// FineGrainedFP8SwiGLUMLP — Round 6: R2 bf16 HMMA core, two SEPARATE kernels
// (plain / fused) so the fused SwiGLU epilogue cannot raise register pressure
// in the gate/down GEMM mainloops.
//
//   detect      : classify fp8-weight storage
//   convert_w   : weights -> exact bf16
//   fq_x        : x -> bf16-quantized values + per-(row,128grp) fp32 scale
//   gemm_plain  : C = Aq @ Bq^T (fp32 out)            [gate, down]
//   gemm_fused  : same + epilogue h=silu(gate)*up -> e4m3->bf16 + scales [up]
// ============================================================================

namespace {

constexpr int MM = 4096, HH = 4096, II = 14336, QB = 128;
constexpr float FP8_MAX = 448.0f;
constexpr int STAGES = 3;
constexpr int STAGE_B = 65536;                    // 32KB A + 32KB B (bf16 128x128)
constexpr int SMEM_SZ = STAGES * STAGE_B;         // 192 KB

// ------------------------------- scratch -----------------------------------
__device__ int           g_flag;
__device__ __nv_bfloat16 g_xb[(size_t)MM * HH];
__device__ float         g_xs[(size_t)MM * (HH / QB)];
__device__ __nv_bfloat16 g_gw[(size_t)II * HH];
__device__ __nv_bfloat16 g_uw[(size_t)II * HH];
__device__ __nv_bfloat16 g_dw[(size_t)HH * II];
__device__ float         g_gate[(size_t)MM * II];
__device__ __nv_bfloat16 g_hb[(size_t)MM * II];
__device__ float         g_hs[(size_t)MM * (II / QB)];

// --------------------------- PTX helpers -----------------------------------
__device__ __forceinline__ uint32_t smem_u32(const void* p) {
    uint32_t a;
    asm("{ .reg .u64 t; cvta.to.shared.u64 t, %1; cvt.u32.u64 %0, t; }" : "=r"(a) : "l"(p));
    return a;
}
__device__ __forceinline__ void cp16(uint32_t dst, const void* src) {
    asm volatile("cp.async.cg.shared.global [%0], [%1], 16;" :: "r"(dst), "l"(src));
}
__device__ __forceinline__ void ldsm4(uint32_t* r, uint32_t a) {
    asm volatile("ldmatrix.sync.aligned.m8n8.x4.shared.b16 {%0,%1,%2,%3}, [%4];"
                 : "=r"(r[0]), "=r"(r[1]), "=r"(r[2]), "=r"(r[3]) : "r"(a));
}
__device__ __forceinline__ void mma_bf16(float* d, const uint32_t* a, uint32_t b0, uint32_t b1) {
    asm volatile(
        "mma.sync.aligned.m16n8k16.row.col.f32.bf16.bf16.f32 "
        "{%0,%1,%2,%3}, {%4,%5,%6,%7}, {%8,%9}, {%0,%1,%2,%3};"
        : "+f"(d[0]), "+f"(d[1]), "+f"(d[2]), "+f"(d[3])
        : "r"(a[0]), "r"(a[1]), "r"(a[2]), "r"(a[3]), "r"(b0), "r"(b1));
}
__device__ __forceinline__ __nv_bfloat16 f8_to_bf16(uint8_t bits) {
    __nv_fp8_e4m3 v; v.__x = bits;
    return __float2bfloat16(float(v));
}

// ------------------------------ aux kernels --------------------------------
__global__ void detect_kernel(const unsigned* __restrict__ w) {
    int ok = 1;
    for (int i = threadIdx.x; i < 256; i += 32)
        if (w[i] & 0x000FFFFFu) ok = 0;
    ok = __all_sync(0xffffffffu, ok) ? 1 : 0;
    if (threadIdx.x == 0) g_flag = ok;
}

__global__ void convert_w_kernel(const void* __restrict__ w, __nv_bfloat16* __restrict__ out,
                                 size_t n4) {
    for (size_t i = (size_t)blockIdx.x * blockDim.x + threadIdx.x; i < n4;
         i += (size_t)gridDim.x * blockDim.x) {
        __nv_bfloat16 o[4];
        if (g_flag) {
            float4 v = reinterpret_cast<const float4*>(w)[i];
            o[0] = __float2bfloat16(float(__nv_fp8_e4m3(v.x)));
            o[1] = __float2bfloat16(float(__nv_fp8_e4m3(v.y)));
            o[2] = __float2bfloat16(float(__nv_fp8_e4m3(v.z)));
            o[3] = __float2bfloat16(float(__nv_fp8_e4m3(v.w)));
        } else {
            uchar4 v = reinterpret_cast<const uchar4*>(w)[i];
            o[0] = f8_to_bf16(v.x); o[1] = f8_to_bf16(v.y);
            o[2] = f8_to_bf16(v.z); o[3] = f8_to_bf16(v.w);
        }
        reinterpret_cast<uint2*>(out)[i] = *reinterpret_cast<uint2*>(o);
    }
}

// x -> bf16 quantized values + scales. One warp per (row, 128-col group).
__global__ void fq_x_kernel(const float* __restrict__ x, __nv_bfloat16* __restrict__ q,
                            float* __restrict__ sc, int cols) {
    int warp = (blockIdx.x * blockDim.x + threadIdx.x) >> 5;
    int lane = threadIdx.x & 31;
    int ng = cols / QB;
    int row = warp / ng, grp = warp % ng;
    size_t off = (size_t)row * cols + grp * QB;
    float4 v = reinterpret_cast<const float4*>(x + off)[lane];
    float amax = fmaxf(fmaxf(fabsf(v.x), fabsf(v.y)), fmaxf(fabsf(v.z), fabsf(v.w)));
#pragma unroll
    for (int o = 16; o; o >>= 1)
        amax = fmaxf(amax, __shfl_xor_sync(0xffffffffu, amax, o));
    float scale = fmaxf(amax / FP8_MAX, 1e-12f);
    __nv_bfloat16 u[4];
    u[0] = __float2bfloat16(float(__nv_fp8_e4m3(fminf(fmaxf(v.x / scale, -FP8_MAX), FP8_MAX))));
    u[1] = __float2bfloat16(float(__nv_fp8_e4m3(fminf(fmaxf(v.y / scale, -FP8_MAX), FP8_MAX))));
    u[2] = __float2bfloat16(float(__nv_fp8_e4m3(fminf(fmaxf(v.z / scale, -FP8_MAX), FP8_MAX))));
    u[3] = __float2bfloat16(float(__nv_fp8_e4m3(fminf(fmaxf(v.w / scale, -FP8_MAX), FP8_MAX))));
    reinterpret_cast<uint2*>(q + off)[lane] = *reinterpret_cast<uint2*>(u);
    if (lane == 0) sc[(size_t)row * ng + grp] = scale;
}

// ----------------------- shared GEMM mainloop (macro body) ------------------
// Defined as a function template over an epilogue functor so the two kernels
// compile as fully separate entities with independent register allocation.

struct EpiPlain {
    float* C;
    __device__ __forceinline__ void run(float full[2][4][4], int bm, int bn, int N,
                                        int wm, int wn, int lane, int tid, char* smem) const {
#pragma unroll
        for (int t = 0; t < 2; t++)
#pragma unroll
            for (int h = 0; h < 2; h++) {
                int row = bm + wm * 32 + t * 16 + h * 8 + (lane >> 2);
#pragma unroll
                for (int j = 0; j < 4; j++) {
                    int col = bn + wn * 32 + j * 8 + (lane & 3) * 2;
                    *reinterpret_cast<float2*>(C + (size_t)row * N + col) =
                        make_float2(full[t][j][2 * h], full[t][j][2 * h + 1]);
                }
            }
    }
};

struct EpiFused {
    const float* GateIn;
    __nv_bfloat16* Hb;
    float* Hs;
    int nb;                                       // blockIdx.y
    __device__ __forceinline__ void run(float full[2][4][4], int bm, int bn, int N,
                                        int wm, int wn, int lane, int tid, char* smem) const {
        int* smax = reinterpret_cast<int*>(smem);
        if (tid < 128) smax[tid] = 0;
        __syncthreads();
#pragma unroll
        for (int t = 0; t < 2; t++)
#pragma unroll
            for (int h = 0; h < 2; h++) {
                int rl = wm * 32 + t * 16 + h * 8 + (lane >> 2);
                int row = bm + rl;
                float lm = 0.0f;
#pragma unroll
                for (int j = 0; j < 4; j++) {
                    int col = bn + wn * 32 + j * 8 + (lane & 3) * 2;
                    float2 g = *reinterpret_cast<const float2*>(GateIn + (size_t)row * N + col);
                    float h0 = g.x * (1.0f / (1.0f + expf(-g.x))) * full[t][j][2 * h];
                    float h1 = g.y * (1.0f / (1.0f + expf(-g.y))) * full[t][j][2 * h + 1];
                    full[t][j][2 * h] = h0;
                    full[t][j][2 * h + 1] = h1;
                    lm = fmaxf(lm, fmaxf(fabsf(h0), fabsf(h1)));
                }
                atomicMax(&smax[rl], __float_as_int(lm));
            }
        __syncthreads();
#pragma unroll
        for (int t = 0; t < 2; t++)
#pragma unroll
            for (int h = 0; h < 2; h++) {
                int rl = wm * 32 + t * 16 + h * 8 + (lane >> 2);
                int row = bm + rl;
                float scale = fmaxf(__int_as_float(smax[rl]) / FP8_MAX, 1e-12f);
#pragma unroll
                for (int j = 0; j < 4; j++) {
                    int col = bn + wn * 32 + j * 8 + (lane & 3) * 2;
                    __nv_bfloat16 q[2];
                    q[0] = __float2bfloat16(float(__nv_fp8_e4m3(
                        fminf(fmaxf(full[t][j][2 * h] / scale, -FP8_MAX), FP8_MAX))));
                    q[1] = __float2bfloat16(float(__nv_fp8_e4m3(
                        fminf(fmaxf(full[t][j][2 * h + 1] / scale, -FP8_MAX), FP8_MAX))));
                    *reinterpret_cast<uint32_t*>(Hb + (size_t)row * N + col) =
                        *reinterpret_cast<uint32_t*>(q);
                }
                if (wn == 0 && (lane & 3) == 0)
                    Hs[(size_t)row * (N / QB) + nb] = scale;
            }
    }
};

template <typename Epi>
__device__ __forceinline__ void gemm_body(
    const __nv_bfloat16* __restrict__ A, const __nv_bfloat16* __restrict__ B,
    const float* __restrict__ Asc, const float* __restrict__ Wsc,
    int N, int K, const Epi& epi, char* smem)
{
    const uint32_t sb = smem_u32(smem);
    const int tid = threadIdx.x, lane = tid & 31, wid = tid >> 5;
    const int wm = wid >> 2, wn = wid & 3;            // 4x4 warp grid
    const int bm = blockIdx.x * 128, bn = blockIdx.y * 128;
    const int nch = K >> 7;

    auto load_stage = [&](int s, int c) {
        const uint32_t base = sb + (uint32_t)s * STAGE_B;
#pragma unroll
        for (int i = 0; i < 4; i++) {
            int idx = tid + (i << 9);                 // 0..2047
            int row = idx >> 4, ch = idx & 15;
            uint32_t dst = base + (uint32_t)(row << 8) + (uint32_t)((ch ^ (row & 7)) << 4);
            cp16(dst, A + (size_t)(bm + row) * K + c * 128 + ch * 8);
        }
#pragma unroll
        for (int i = 0; i < 4; i++) {
            int idx = tid + (i << 9);
            int row = idx >> 4, ch = idx & 15;
            uint32_t dst = base + 32768u + (uint32_t)(row << 8) + (uint32_t)((ch ^ (row & 7)) << 4);
            cp16(dst, B + (size_t)(bn + row) * K + c * 128 + ch * 8);
        }
        asm volatile("cp.async.commit_group;");
    };

    float full[2][4][4];
#pragma unroll
    for (int t = 0; t < 2; t++)
#pragma unroll
        for (int j = 0; j < 4; j++)
#pragma unroll
            for (int r = 0; r < 4; r++) full[t][j][r] = 0.0f;

    for (int c = 0; c < STAGES - 1; c++) load_stage(c, c);

    const float* wsc = Wsc + (size_t)blockIdx.y * nch;

    for (int c = 0; c < nch; c++) {
        asm volatile("cp.async.wait_group %0;" :: "n"(STAGES - 2));
        __syncthreads();

        {   // issue next chunk into the stage freed last iteration
            int cl = c + STAGES - 1;
            if (cl < nch) load_stage(cl % STAGES, cl);
            else asm volatile("cp.async.commit_group;");
        }

        const uint32_t Ab = sb + (uint32_t)(c % STAGES) * STAGE_B;
        const uint32_t Bb = Ab + 32768u;

        float cacc[2][4][4];
#pragma unroll
        for (int t = 0; t < 2; t++)
#pragma unroll
            for (int j = 0; j < 4; j++)
#pragma unroll
                for (int r = 0; r < 4; r++) cacc[t][j][r] = 0.0f;

#pragma unroll
        for (int ks = 0; ks < 8; ks++) {
            uint32_t a[2][4], b[2][4];
#pragma unroll
            for (int t = 0; t < 2; t++) {
                int mrow = wm * 32 + t * 16 + (lane & 15);
                int chn = ((ks << 1) + (lane >> 4)) ^ (mrow & 7);
                ldsm4(a[t], Ab + (uint32_t)(mrow << 8) + (uint32_t)(chn << 4));
            }
#pragma unroll
            for (int p = 0; p < 2; p++) {
                int nrow = wn * 32 + p * 16 + (lane & 15);
                int chn = ((ks << 1) + (lane >> 4)) ^ (nrow & 7);
                ldsm4(b[p], Bb + (uint32_t)(nrow << 8) + (uint32_t)(chn << 4));
            }
#pragma unroll
            for (int t = 0; t < 2; t++)
#pragma unroll
                for (int j = 0; j < 4; j++) {
                    int p = j >> 1, o = j & 1;
                    mma_bf16(cacc[t][j], a[t], b[p][o], b[p][o + 2]);
                }
        }

        // promote this 128-K block with exact fp32 scales (R2 placement)
        const float sw = wsc[c];
#pragma unroll
        for (int t = 0; t < 2; t++)
#pragma unroll
            for (int h = 0; h < 2; h++) {
                int row = bm + wm * 32 + t * 16 + h * 8 + (lane >> 2);
                float s = Asc[(size_t)row * nch + c] * sw;
#pragma unroll
                for (int j = 0; j < 4; j++) {
                    full[t][j][2 * h]     = fmaf(s, cacc[t][j][2 * h],     full[t][j][2 * h]);
                    full[t][j][2 * h + 1] = fmaf(s, cacc[t][j][2 * h + 1], full[t][j][2 * h + 1]);
                }
            }
        __syncthreads();
    }

    epi.run(full, bm, bn, N, wm, wn, lane, tid, smem);
}

__global__ void __launch_bounds__(512, 1) gemm_plain_kernel(
    const __nv_bfloat16* __restrict__ A, const __nv_bfloat16* __restrict__ B,
    const float* __restrict__ Asc, const float* __restrict__ Wsc,
    float* __restrict__ C, int N, int K)
{
    extern __shared__ char smem[];
    EpiPlain epi{C};
    gemm_body(A, B, Asc, Wsc, N, K, epi, smem);
}

__global__ void __launch_bounds__(512, 1) gemm_fused_kernel(
    const __nv_bfloat16* __restrict__ A, const __nv_bfloat16* __restrict__ B,
    const float* __restrict__ Asc, const float* __restrict__ Wsc,
    const float* __restrict__ GateIn,
    __nv_bfloat16* __restrict__ Hb, float* __restrict__ Hs,
    int N, int K)
{
    extern __shared__ char smem[];
    EpiFused epi{GateIn, Hb, Hs, (int)blockIdx.y};
    gemm_body(A, B, Asc, Wsc, N, K, epi, smem);
}

}  // namespace

// ============================================================================
extern "C" void kernel_launch(void* const* d_in, const int* in_sizes, int n_in,
                              void* d_out, int out_size) {
    const float* x  = (const float*)d_in[0];
    const void*  gw = d_in[1];
    const float* gs = (const float*)d_in[2];
    const void*  uw = d_in[3];
    const float* us = (const float*)d_in[4];
    const void*  dw = d_in[5];
    const float* ds = (const float*)d_in[6];
    float* out = (float*)d_out;

    __nv_bfloat16 *xb, *gwb, *uwb, *dwb, *hb;
    float *xs, *gate, *hs;
    cudaGetSymbolAddress((void**)&xb,  g_xb);
    cudaGetSymbolAddress((void**)&xs,  g_xs);
    cudaGetSymbolAddress((void**)&gwb, g_gw);
    cudaGetSymbolAddress((void**)&uwb, g_uw);
    cudaGetSymbolAddress((void**)&dwb, g_dw);
    cudaGetSymbolAddress((void**)&gate, g_gate);
    cudaGetSymbolAddress((void**)&hb,  g_hb);
    cudaGetSymbolAddress((void**)&hs,  g_hs);

    cudaFuncSetAttribute(gemm_plain_kernel, cudaFuncAttributeMaxDynamicSharedMemorySize, SMEM_SZ);
    cudaFuncSetAttribute(gemm_fused_kernel, cudaFuncAttributeMaxDynamicSharedMemorySize, SMEM_SZ);

    detect_kernel<<<1, 32>>>((const unsigned*)gw);

    {   // weights -> exact bf16
        size_t n4 = (size_t)II * HH / 4;
        convert_w_kernel<<<2048, 256>>>(gw, gwb, n4);
        convert_w_kernel<<<2048, 256>>>(uw, uwb, n4);
        convert_w_kernel<<<2048, 256>>>(dw, dwb, n4);
    }

    fq_x_kernel<<<MM * (HH / QB) / 8, 256>>>(x, xb, xs, HH);

    // gate GEMM -> fp32 gate buffer
    gemm_plain_kernel<<<dim3(MM / 128, II / 128), 512, SMEM_SZ>>>(
        xb, gwb, xs, gs, gate, II, HH);
    // up GEMM with fused swiglu+fake-quant -> hb/hs
    gemm_fused_kernel<<<dim3(MM / 128, II / 128), 512, SMEM_SZ>>>(
        xb, uwb, xs, us, gate, hb, hs, II, HH);
    // down GEMM -> fp32 out
    gemm_plain_kernel<<<dim3(MM / 128, HH / 128), 512, SMEM_SZ>>>(
        hb, dwb, hs, ds, out, HH, II);
}

// round 8
// speedup vs baseline: 1.1312x; 1.0558x over previous
#include <cuda_runtime.h>
#include <cuda_fp8.h>
#include <cuda_bf16.h>
#include <cstdint>

// ============================================================================
// FineGrainedFP8SwiGLUMLP — Round 7: exact R2 GEMM core (untouched local
// optimum) + side-stream overlap of weight conversion + merged gate/up GEMM.
//
//   detect      : classify fp8-weight storage
//   convert_w   : weights -> exact bf16   (up/down on side stream)
//   fq_x        : x -> bf16-quantized values + per-(row,128grp) fp32 scale
//   gemm_dual   : gate & up GEMMs in one launch (grid.y selects weights)
//   combine_fq  : hidden = fq(silu(gate)*up) -> bf16 + scales
//   gemm_plain  : down GEMM
// ============================================================================

namespace {

constexpr int MM = 4096, HH = 4096, II = 14336, QB = 128;
constexpr float FP8_MAX = 448.0f;
constexpr int STAGES = 3;
constexpr int STAGE_B = 65536;                    // 32KB A + 32KB B (bf16 128x128)
constexpr int SMEM_SZ = STAGES * STAGE_B;         // 192 KB

// ------------------------------- scratch -----------------------------------
__device__ int           g_flag;
__device__ __nv_bfloat16 g_xb[(size_t)MM * HH];
__device__ float         g_xs[(size_t)MM * (HH / QB)];
__device__ __nv_bfloat16 g_gw[(size_t)II * HH];
__device__ __nv_bfloat16 g_uw[(size_t)II * HH];
__device__ __nv_bfloat16 g_dw[(size_t)HH * II];
__device__ float         g_gate[(size_t)MM * II];
__device__ float         g_up[(size_t)MM * II];
__device__ __nv_bfloat16 g_hb[(size_t)MM * II];
__device__ float         g_hs[(size_t)MM * (II / QB)];

// --------------------------- PTX helpers -----------------------------------
__device__ __forceinline__ uint32_t smem_u32(const void* p) {
    uint32_t a;
    asm("{ .reg .u64 t; cvta.to.shared.u64 t, %1; cvt.u32.u64 %0, t; }" : "=r"(a) : "l"(p));
    return a;
}
__device__ __forceinline__ void cp16(uint32_t dst, const void* src) {
    asm volatile("cp.async.cg.shared.global [%0], [%1], 16;" :: "r"(dst), "l"(src));
}
__device__ __forceinline__ void ldsm4(uint32_t* r, uint32_t a) {
    asm volatile("ldmatrix.sync.aligned.m8n8.x4.shared.b16 {%0,%1,%2,%3}, [%4];"
                 : "=r"(r[0]), "=r"(r[1]), "=r"(r[2]), "=r"(r[3]) : "r"(a));
}
__device__ __forceinline__ void mma_bf16(float* d, const uint32_t* a, uint32_t b0, uint32_t b1) {
    asm volatile(
        "mma.sync.aligned.m16n8k16.row.col.f32.bf16.bf16.f32 "
        "{%0,%1,%2,%3}, {%4,%5,%6,%7}, {%8,%9}, {%0,%1,%2,%3};"
        : "+f"(d[0]), "+f"(d[1]), "+f"(d[2]), "+f"(d[3])
        : "r"(a[0]), "r"(a[1]), "r"(a[2]), "r"(a[3]), "r"(b0), "r"(b1));
}
__device__ __forceinline__ __nv_bfloat16 f8_to_bf16(uint8_t bits) {
    __nv_fp8_e4m3 v; v.__x = bits;
    return __float2bfloat16(float(v));
}

// ------------------------------ aux kernels --------------------------------
__global__ void detect_kernel(const unsigned* __restrict__ w) {
    int ok = 1;
    for (int i = threadIdx.x; i < 256; i += 32)
        if (w[i] & 0x000FFFFFu) ok = 0;
    ok = __all_sync(0xffffffffu, ok) ? 1 : 0;
    if (threadIdx.x == 0) g_flag = ok;
}

__global__ void convert_w_kernel(const void* __restrict__ w, __nv_bfloat16* __restrict__ out,
                                 size_t n4) {
    for (size_t i = (size_t)blockIdx.x * blockDim.x + threadIdx.x; i < n4;
         i += (size_t)gridDim.x * blockDim.x) {
        __nv_bfloat16 o[4];
        if (g_flag) {
            float4 v = reinterpret_cast<const float4*>(w)[i];
            o[0] = __float2bfloat16(float(__nv_fp8_e4m3(v.x)));
            o[1] = __float2bfloat16(float(__nv_fp8_e4m3(v.y)));
            o[2] = __float2bfloat16(float(__nv_fp8_e4m3(v.z)));
            o[3] = __float2bfloat16(float(__nv_fp8_e4m3(v.w)));
        } else {
            uchar4 v = reinterpret_cast<const uchar4*>(w)[i];
            o[0] = f8_to_bf16(v.x); o[1] = f8_to_bf16(v.y);
            o[2] = f8_to_bf16(v.z); o[3] = f8_to_bf16(v.w);
        }
        reinterpret_cast<uint2*>(out)[i] = *reinterpret_cast<uint2*>(o);
    }
}

// x -> bf16 quantized values + scales. One warp per (row, 128-col group).
__global__ void fq_x_kernel(const float* __restrict__ x, __nv_bfloat16* __restrict__ q,
                            float* __restrict__ sc, int cols) {
    int warp = (blockIdx.x * blockDim.x + threadIdx.x) >> 5;
    int lane = threadIdx.x & 31;
    int ng = cols / QB;
    int row = warp / ng, grp = warp % ng;
    size_t off = (size_t)row * cols + grp * QB;
    float4 v = reinterpret_cast<const float4*>(x + off)[lane];
    float amax = fmaxf(fmaxf(fabsf(v.x), fabsf(v.y)), fmaxf(fabsf(v.z), fabsf(v.w)));
#pragma unroll
    for (int o = 16; o; o >>= 1)
        amax = fmaxf(amax, __shfl_xor_sync(0xffffffffu, amax, o));
    float scale = fmaxf(amax / FP8_MAX, 1e-12f);
    __nv_bfloat16 u[4];
    u[0] = __float2bfloat16(float(__nv_fp8_e4m3(fminf(fmaxf(v.x / scale, -FP8_MAX), FP8_MAX))));
    u[1] = __float2bfloat16(float(__nv_fp8_e4m3(fminf(fmaxf(v.y / scale, -FP8_MAX), FP8_MAX))));
    u[2] = __float2bfloat16(float(__nv_fp8_e4m3(fminf(fmaxf(v.z / scale, -FP8_MAX), FP8_MAX))));
    u[3] = __float2bfloat16(float(__nv_fp8_e4m3(fminf(fmaxf(v.w / scale, -FP8_MAX), FP8_MAX))));
    reinterpret_cast<uint2*>(q + off)[lane] = *reinterpret_cast<uint2*>(u);
    if (lane == 0) sc[(size_t)row * ng + grp] = scale;
}

// hidden = fq(silu(gate)*up) -> bf16 + scales (R2 combine)
__global__ void combine_fq_kernel(const float* __restrict__ gate, const float* __restrict__ up,
                                  __nv_bfloat16* __restrict__ q, float* __restrict__ sc, int cols) {
    int warp = (blockIdx.x * blockDim.x + threadIdx.x) >> 5;
    int lane = threadIdx.x & 31;
    int ng = cols / QB;
    int row = warp / ng, grp = warp % ng;
    size_t off = (size_t)row * cols + grp * QB;
    float4 g = reinterpret_cast<const float4*>(gate + off)[lane];
    float4 u = reinterpret_cast<const float4*>(up + off)[lane];
    float h[4];
    h[0] = g.x * (1.0f / (1.0f + expf(-g.x))) * u.x;
    h[1] = g.y * (1.0f / (1.0f + expf(-g.y))) * u.y;
    h[2] = g.z * (1.0f / (1.0f + expf(-g.z))) * u.z;
    h[3] = g.w * (1.0f / (1.0f + expf(-g.w))) * u.w;
    float amax = fmaxf(fmaxf(fabsf(h[0]), fabsf(h[1])), fmaxf(fabsf(h[2]), fabsf(h[3])));
#pragma unroll
    for (int o = 16; o; o >>= 1)
        amax = fmaxf(amax, __shfl_xor_sync(0xffffffffu, amax, o));
    float scale = fmaxf(amax / FP8_MAX, 1e-12f);
    __nv_bfloat16 o4[4];
#pragma unroll
    for (int i = 0; i < 4; i++)
        o4[i] = __float2bfloat16(float(__nv_fp8_e4m3(fminf(fmaxf(h[i] / scale, -FP8_MAX), FP8_MAX))));
    reinterpret_cast<uint2*>(q + off)[lane] = *reinterpret_cast<uint2*>(o4);
    if (lane == 0) sc[(size_t)row * ng + grp] = scale;
}

// ----------------------- shared GEMM body (R2, untouched) ------------------
__device__ __forceinline__ void gemm_body(
    const __nv_bfloat16* __restrict__ A, const __nv_bfloat16* __restrict__ B,
    const float* __restrict__ Asc, const float* __restrict__ Wsc,
    float* __restrict__ C, int N, int K, int nb, char* smem)
{
    const uint32_t sb = smem_u32(smem);
    const int tid = threadIdx.x, lane = tid & 31, wid = tid >> 5;
    const int wm = wid >> 2, wn = wid & 3;            // 4x4 warp grid
    const int bm = blockIdx.x * 128, bn = nb * 128;
    const int nch = K >> 7;

    auto load_stage = [&](int s, int c) {
        const uint32_t base = sb + (uint32_t)s * STAGE_B;
#pragma unroll
        for (int i = 0; i < 4; i++) {
            int idx = tid + (i << 9);                 // 0..2047
            int row = idx >> 4, ch = idx & 15;
            uint32_t dst = base + (uint32_t)(row << 8) + (uint32_t)((ch ^ (row & 7)) << 4);
            cp16(dst, A + (size_t)(bm + row) * K + c * 128 + ch * 8);
        }
#pragma unroll
        for (int i = 0; i < 4; i++) {
            int idx = tid + (i << 9);
            int row = idx >> 4, ch = idx & 15;
            uint32_t dst = base + 32768u + (uint32_t)(row << 8) + (uint32_t)((ch ^ (row & 7)) << 4);
            cp16(dst, B + (size_t)(bn + row) * K + c * 128 + ch * 8);
        }
        asm volatile("cp.async.commit_group;");
    };

    float full[2][4][4];
#pragma unroll
    for (int t = 0; t < 2; t++)
#pragma unroll
        for (int j = 0; j < 4; j++)
#pragma unroll
            for (int r = 0; r < 4; r++) full[t][j][r] = 0.0f;

    for (int c = 0; c < STAGES - 1; c++) load_stage(c, c);

    const float* wsc = Wsc + (size_t)nb * nch;

    for (int c = 0; c < nch; c++) {
        asm volatile("cp.async.wait_group %0;" :: "n"(STAGES - 2));
        __syncthreads();

        {   // issue next chunk into the stage freed last iteration
            int cl = c + STAGES - 1;
            if (cl < nch) load_stage(cl % STAGES, cl);
            else asm volatile("cp.async.commit_group;");
        }

        const uint32_t Ab = sb + (uint32_t)(c % STAGES) * STAGE_B;
        const uint32_t Bb = Ab + 32768u;

        float cacc[2][4][4];
#pragma unroll
        for (int t = 0; t < 2; t++)
#pragma unroll
            for (int j = 0; j < 4; j++)
#pragma unroll
                for (int r = 0; r < 4; r++) cacc[t][j][r] = 0.0f;

#pragma unroll
        for (int ks = 0; ks < 8; ks++) {
            uint32_t a[2][4], b[2][4];
#pragma unroll
            for (int t = 0; t < 2; t++) {
                int mrow = wm * 32 + t * 16 + (lane & 15);
                int chn = ((ks << 1) + (lane >> 4)) ^ (mrow & 7);
                ldsm4(a[t], Ab + (uint32_t)(mrow << 8) + (uint32_t)(chn << 4));
            }
#pragma unroll
            for (int p = 0; p < 2; p++) {
                int nrow = wn * 32 + p * 16 + (lane & 15);
                int chn = ((ks << 1) + (lane >> 4)) ^ (nrow & 7);
                ldsm4(b[p], Bb + (uint32_t)(nrow << 8) + (uint32_t)(chn << 4));
            }
#pragma unroll
            for (int t = 0; t < 2; t++)
#pragma unroll
                for (int j = 0; j < 4; j++) {
                    int p = j >> 1, o = j & 1;
                    mma_bf16(cacc[t][j], a[t], b[p][o], b[p][o + 2]);
                }
        }

        // promote this 128-K block with exact fp32 scales
        const float sw = wsc[c];
#pragma unroll
        for (int t = 0; t < 2; t++)
#pragma unroll
            for (int h = 0; h < 2; h++) {
                int row = bm + wm * 32 + t * 16 + h * 8 + (lane >> 2);
                float s = Asc[(size_t)row * nch + c] * sw;
#pragma unroll
                for (int j = 0; j < 4; j++) {
                    full[t][j][2 * h]     = fmaf(s, cacc[t][j][2 * h],     full[t][j][2 * h]);
                    full[t][j][2 * h + 1] = fmaf(s, cacc[t][j][2 * h + 1], full[t][j][2 * h + 1]);
                }
            }
        __syncthreads();
    }

    // plain fp32 epilogue
#pragma unroll
    for (int t = 0; t < 2; t++)
#pragma unroll
        for (int h = 0; h < 2; h++) {
            int row = bm + wm * 32 + t * 16 + h * 8 + (lane >> 2);
#pragma unroll
            for (int j = 0; j < 4; j++) {
                int col = bn + wn * 32 + j * 8 + (lane & 3) * 2;
                *reinterpret_cast<float2*>(C + (size_t)row * N + col) =
                    make_float2(full[t][j][2 * h], full[t][j][2 * h + 1]);
            }
        }
}

__global__ void __launch_bounds__(512, 1) gemm_plain_kernel(
    const __nv_bfloat16* __restrict__ A, const __nv_bfloat16* __restrict__ B,
    const float* __restrict__ Asc, const float* __restrict__ Wsc,
    float* __restrict__ C, int N, int K)
{
    extern __shared__ char smem[];
    gemm_body(A, B, Asc, Wsc, C, N, K, blockIdx.y, smem);
}

// gate & up in one launch: grid.y in [0,224); y<112 -> gate, else -> up.
__global__ void __launch_bounds__(512, 1) gemm_dual_kernel(
    const __nv_bfloat16* __restrict__ A,
    const __nv_bfloat16* __restrict__ Bg, const __nv_bfloat16* __restrict__ Bu,
    const float* __restrict__ Asc,
    const float* __restrict__ Wg, const float* __restrict__ Wu,
    float* __restrict__ Cg, float* __restrict__ Cu, int K)
{
    extern __shared__ char smem[];
    const int half = II / 128;                        // 112
    const bool is_up = (int)blockIdx.y >= half;
    const __nv_bfloat16* B = is_up ? Bu : Bg;
    const float* W = is_up ? Wu : Wg;
    float* C = is_up ? Cu : Cg;
    const int nb = is_up ? (int)blockIdx.y - half : (int)blockIdx.y;
    gemm_body(A, B, Asc, W, C, II, K, nb, smem);
}

// --------------- side stream / events (static init, created once) ----------
struct AsyncCtx {
    cudaStream_t s1;
    cudaEvent_t e_detect, e_up, e_down;
    AsyncCtx() {
        cudaStreamCreateWithFlags(&s1, cudaStreamNonBlocking);
        cudaEventCreateWithFlags(&e_detect, cudaEventDisableTiming);
        cudaEventCreateWithFlags(&e_up, cudaEventDisableTiming);
        cudaEventCreateWithFlags(&e_down, cudaEventDisableTiming);
    }
};
AsyncCtx g_ctx;

}  // namespace

// ============================================================================
extern "C" void kernel_launch(void* const* d_in, const int* in_sizes, int n_in,
                              void* d_out, int out_size) {
    const float* x  = (const float*)d_in[0];
    const void*  gw = d_in[1];
    const float* gs = (const float*)d_in[2];
    const void*  uw = d_in[3];
    const float* us = (const float*)d_in[4];
    const void*  dw = d_in[5];
    const float* ds = (const float*)d_in[6];
    float* out = (float*)d_out;

    __nv_bfloat16 *xb, *gwb, *uwb, *dwb, *hb;
    float *xs, *gate, *up, *hs;
    cudaGetSymbolAddress((void**)&xb,  g_xb);
    cudaGetSymbolAddress((void**)&xs,  g_xs);
    cudaGetSymbolAddress((void**)&gwb, g_gw);
    cudaGetSymbolAddress((void**)&uwb, g_uw);
    cudaGetSymbolAddress((void**)&dwb, g_dw);
    cudaGetSymbolAddress((void**)&gate, g_gate);
    cudaGetSymbolAddress((void**)&up,   g_up);
    cudaGetSymbolAddress((void**)&hb,  g_hb);
    cudaGetSymbolAddress((void**)&hs,  g_hs);

    cudaFuncSetAttribute(gemm_plain_kernel, cudaFuncAttributeMaxDynamicSharedMemorySize, SMEM_SZ);
    cudaFuncSetAttribute(gemm_dual_kernel,  cudaFuncAttributeMaxDynamicSharedMemorySize, SMEM_SZ);

    const size_t n4 = (size_t)II * HH / 4;

    // main stream: detect, then fork side stream for up/down weight conversion
    detect_kernel<<<1, 32>>>((const unsigned*)gw);
    cudaEventRecord(g_ctx.e_detect, 0);
    cudaStreamWaitEvent(g_ctx.s1, g_ctx.e_detect, 0);

    convert_w_kernel<<<2048, 256, 0, g_ctx.s1>>>(uw, uwb, n4);
    cudaEventRecord(g_ctx.e_up, g_ctx.s1);
    convert_w_kernel<<<2048, 256, 0, g_ctx.s1>>>(dw, dwb, n4);
    cudaEventRecord(g_ctx.e_down, g_ctx.s1);

    // main stream: gate weights + activation quantization
    convert_w_kernel<<<2048, 256>>>(gw, gwb, n4);
    fq_x_kernel<<<MM * (HH / QB) / 8, 256>>>(x, xb, xs, HH);

    // join: up weights needed by the dual GEMM
    cudaStreamWaitEvent(0, g_ctx.e_up, 0);
    gemm_dual_kernel<<<dim3(MM / 128, 2 * (II / 128)), 512, SMEM_SZ>>>(
        xb, gwb, uwb, xs, gs, us, gate, up, HH);

    combine_fq_kernel<<<MM * (II / QB) / 8, 256>>>(gate, up, hb, hs, II);

    // join: down weights needed by the down GEMM (hidden under dual GEMM)
    cudaStreamWaitEvent(0, g_ctx.e_down, 0);
    gemm_plain_kernel<<<dim3(MM / 128, HH / 128), 512, SMEM_SZ>>>(
        hb, dwb, hs, ds, out, HH, II);
}

// round 11
// speedup vs baseline: 1.1432x; 1.0106x over previous
#include <cuda_runtime.h>
#include <cuda_fp8.h>
#include <cuda_bf16.h>
#include <cstdint>

// ============================================================================
// FineGrainedFP8SwiGLUMLP — Round 9 (fix of R9 capture failure):
//   - R2 bf16 HMMA GEMM core, single top-barrier multistage loop
//   - weight conversions overlapped on side stream s1 (event-forked)
//   - fq_x on side stream s2, NOW properly event-forked from the capture
//     origin stream (the R9 bug: s2 was never forked -> capture error)
//   - merged gate/up dual GEMM, combine kernel, down GEMM
// ============================================================================

namespace {

constexpr int MM = 4096, HH = 4096, II = 14336, QB = 128;
constexpr float FP8_MAX = 448.0f;
constexpr int STAGES = 3;
constexpr int STAGE_B = 65536;                    // 32KB A + 32KB B (bf16 128x128)
constexpr int SMEM_SZ = STAGES * STAGE_B;         // 192 KB

// ------------------------------- scratch -----------------------------------
__device__ int           g_flag;
__device__ __nv_bfloat16 g_xb[(size_t)MM * HH];
__device__ float         g_xs[(size_t)MM * (HH / QB)];
__device__ __nv_bfloat16 g_gw[(size_t)II * HH];
__device__ __nv_bfloat16 g_uw[(size_t)II * HH];
__device__ __nv_bfloat16 g_dw[(size_t)HH * II];
__device__ float         g_gate[(size_t)MM * II];
__device__ float         g_up[(size_t)MM * II];
__device__ __nv_bfloat16 g_hb[(size_t)MM * II];
__device__ float         g_hs[(size_t)MM * (II / QB)];

// --------------------------- PTX helpers -----------------------------------
__device__ __forceinline__ uint32_t smem_u32(const void* p) {
    uint32_t a;
    asm("{ .reg .u64 t; cvta.to.shared.u64 t, %1; cvt.u32.u64 %0, t; }" : "=r"(a) : "l"(p));
    return a;
}
__device__ __forceinline__ void cp16(uint32_t dst, const void* src) {
    asm volatile("cp.async.cg.shared.global [%0], [%1], 16;" :: "r"(dst), "l"(src));
}
__device__ __forceinline__ void ldsm4(uint32_t* r, uint32_t a) {
    asm volatile("ldmatrix.sync.aligned.m8n8.x4.shared.b16 {%0,%1,%2,%3}, [%4];"
                 : "=r"(r[0]), "=r"(r[1]), "=r"(r[2]), "=r"(r[3]) : "r"(a));
}
__device__ __forceinline__ void mma_bf16(float* d, const uint32_t* a, uint32_t b0, uint32_t b1) {
    asm volatile(
        "mma.sync.aligned.m16n8k16.row.col.f32.bf16.bf16.f32 "
        "{%0,%1,%2,%3}, {%4,%5,%6,%7}, {%8,%9}, {%0,%1,%2,%3};"
        : "+f"(d[0]), "+f"(d[1]), "+f"(d[2]), "+f"(d[3])
        : "r"(a[0]), "r"(a[1]), "r"(a[2]), "r"(a[3]), "r"(b0), "r"(b1));
}
__device__ __forceinline__ __nv_bfloat16 f8_to_bf16(uint8_t bits) {
    __nv_fp8_e4m3 v; v.__x = bits;
    return __float2bfloat16(float(v));
}

// ------------------------------ aux kernels --------------------------------
__global__ void detect_kernel(const unsigned* __restrict__ w) {
    int ok = 1;
    for (int i = threadIdx.x; i < 256; i += 32)
        if (w[i] & 0x000FFFFFu) ok = 0;
    ok = __all_sync(0xffffffffu, ok) ? 1 : 0;
    if (threadIdx.x == 0) g_flag = ok;
}

__global__ void convert_w_kernel(const void* __restrict__ w, __nv_bfloat16* __restrict__ out,
                                 size_t n4) {
    for (size_t i = (size_t)blockIdx.x * blockDim.x + threadIdx.x; i < n4;
         i += (size_t)gridDim.x * blockDim.x) {
        __nv_bfloat16 o[4];
        if (g_flag) {
            float4 v = reinterpret_cast<const float4*>(w)[i];
            o[0] = __float2bfloat16(float(__nv_fp8_e4m3(v.x)));
            o[1] = __float2bfloat16(float(__nv_fp8_e4m3(v.y)));
            o[2] = __float2bfloat16(float(__nv_fp8_e4m3(v.z)));
            o[3] = __float2bfloat16(float(__nv_fp8_e4m3(v.w)));
        } else {
            uchar4 v = reinterpret_cast<const uchar4*>(w)[i];
            o[0] = f8_to_bf16(v.x); o[1] = f8_to_bf16(v.y);
            o[2] = f8_to_bf16(v.z); o[3] = f8_to_bf16(v.w);
        }
        reinterpret_cast<uint2*>(out)[i] = *reinterpret_cast<uint2*>(o);
    }
}

// x -> bf16 quantized values + scales. One warp per (row, 128-col group).
__global__ void fq_x_kernel(const float* __restrict__ x, __nv_bfloat16* __restrict__ q,
                            float* __restrict__ sc, int cols) {
    int warp = (blockIdx.x * blockDim.x + threadIdx.x) >> 5;
    int lane = threadIdx.x & 31;
    int ng = cols / QB;
    int row = warp / ng, grp = warp % ng;
    size_t off = (size_t)row * cols + grp * QB;
    float4 v = reinterpret_cast<const float4*>(x + off)[lane];
    float amax = fmaxf(fmaxf(fabsf(v.x), fabsf(v.y)), fmaxf(fabsf(v.z), fabsf(v.w)));
#pragma unroll
    for (int o = 16; o; o >>= 1)
        amax = fmaxf(amax, __shfl_xor_sync(0xffffffffu, amax, o));
    float scale = fmaxf(amax / FP8_MAX, 1e-12f);
    __nv_bfloat16 u[4];
    u[0] = __float2bfloat16(float(__nv_fp8_e4m3(fminf(fmaxf(v.x / scale, -FP8_MAX), FP8_MAX))));
    u[1] = __float2bfloat16(float(__nv_fp8_e4m3(fminf(fmaxf(v.y / scale, -FP8_MAX), FP8_MAX))));
    u[2] = __float2bfloat16(float(__nv_fp8_e4m3(fminf(fmaxf(v.z / scale, -FP8_MAX), FP8_MAX))));
    u[3] = __float2bfloat16(float(__nv_fp8_e4m3(fminf(fmaxf(v.w / scale, -FP8_MAX), FP8_MAX))));
    reinterpret_cast<uint2*>(q + off)[lane] = *reinterpret_cast<uint2*>(u);
    if (lane == 0) sc[(size_t)row * ng + grp] = scale;
}

// hidden = fq(silu(gate)*up) -> bf16 + scales
__global__ void combine_fq_kernel(const float* __restrict__ gate, const float* __restrict__ up,
                                  __nv_bfloat16* __restrict__ q, float* __restrict__ sc, int cols) {
    int warp = (blockIdx.x * blockDim.x + threadIdx.x) >> 5;
    int lane = threadIdx.x & 31;
    int ng = cols / QB;
    int row = warp / ng, grp = warp % ng;
    size_t off = (size_t)row * cols + grp * QB;
    float4 g = reinterpret_cast<const float4*>(gate + off)[lane];
    float4 u = reinterpret_cast<const float4*>(up + off)[lane];
    float h[4];
    h[0] = g.x * (1.0f / (1.0f + expf(-g.x))) * u.x;
    h[1] = g.y * (1.0f / (1.0f + expf(-g.y))) * u.y;
    h[2] = g.z * (1.0f / (1.0f + expf(-g.z))) * u.z;
    h[3] = g.w * (1.0f / (1.0f + expf(-g.w))) * u.w;
    float amax = fmaxf(fmaxf(fabsf(h[0]), fabsf(h[1])), fmaxf(fabsf(h[2]), fabsf(h[3])));
#pragma unroll
    for (int o = 16; o; o >>= 1)
        amax = fmaxf(amax, __shfl_xor_sync(0xffffffffu, amax, o));
    float scale = fmaxf(amax / FP8_MAX, 1e-12f);
    __nv_bfloat16 o4[4];
#pragma unroll
    for (int i = 0; i < 4; i++)
        o4[i] = __float2bfloat16(float(__nv_fp8_e4m3(fminf(fmaxf(h[i] / scale, -FP8_MAX), FP8_MAX))));
    reinterpret_cast<uint2*>(q + off)[lane] = *reinterpret_cast<uint2*>(o4);
    if (lane == 0) sc[(size_t)row * ng + grp] = scale;
}

// ----------------------- shared GEMM body ----------------------------------
__device__ __forceinline__ void gemm_body(
    const __nv_bfloat16* __restrict__ A, const __nv_bfloat16* __restrict__ B,
    const float* __restrict__ Asc, const float* __restrict__ Wsc,
    float* __restrict__ C, int N, int K, int nb, char* smem)
{
    const uint32_t sb = smem_u32(smem);
    const int tid = threadIdx.x, lane = tid & 31, wid = tid >> 5;
    const int wm = wid >> 2, wn = wid & 3;            // 4x4 warp grid
    const int bm = blockIdx.x * 128, bn = nb * 128;
    const int nch = K >> 7;

    auto load_stage = [&](int s, int c) {
        const uint32_t base = sb + (uint32_t)s * STAGE_B;
#pragma unroll
        for (int i = 0; i < 4; i++) {
            int idx = tid + (i << 9);                 // 0..2047
            int row = idx >> 4, ch = idx & 15;
            uint32_t dst = base + (uint32_t)(row << 8) + (uint32_t)((ch ^ (row & 7)) << 4);
            cp16(dst, A + (size_t)(bm + row) * K + c * 128 + ch * 8);
        }
#pragma unroll
        for (int i = 0; i < 4; i++) {
            int idx = tid + (i << 9);
            int row = idx >> 4, ch = idx & 15;
            uint32_t dst = base + 32768u + (uint32_t)(row << 8) + (uint32_t)((ch ^ (row & 7)) << 4);
            cp16(dst, B + (size_t)(bn + row) * K + c * 128 + ch * 8);
        }
        asm volatile("cp.async.commit_group;");
    };

    float full[2][4][4];
#pragma unroll
    for (int t = 0; t < 2; t++)
#pragma unroll
        for (int j = 0; j < 4; j++)
#pragma unroll
            for (int r = 0; r < 4; r++) full[t][j][r] = 0.0f;

    for (int c = 0; c < STAGES - 1; c++) load_stage(c, c);

    const float* wsc = Wsc + (size_t)nb * nch;

    for (int c = 0; c < nch; c++) {
        asm volatile("cp.async.wait_group %0;" :: "n"(STAGES - 2));
        __syncthreads();   // single barrier per chunk: publishes stage c%3 AND
                           // guarantees all warps finished reading stage (c-1)%3
                           // before the load below overwrites it.

        {   // issue next chunk into the stage freed last iteration
            int cl = c + STAGES - 1;
            if (cl < nch) load_stage(cl % STAGES, cl);
            else asm volatile("cp.async.commit_group;");
        }

        const uint32_t Ab = sb + (uint32_t)(c % STAGES) * STAGE_B;
        const uint32_t Bb = Ab + 32768u;

        float cacc[2][4][4];
#pragma unroll
        for (int t = 0; t < 2; t++)
#pragma unroll
            for (int j = 0; j < 4; j++)
#pragma unroll
                for (int r = 0; r < 4; r++) cacc[t][j][r] = 0.0f;

#pragma unroll
        for (int ks = 0; ks < 8; ks++) {
            uint32_t a[2][4], b[2][4];
#pragma unroll
            for (int t = 0; t < 2; t++) {
                int mrow = wm * 32 + t * 16 + (lane & 15);
                int chn = ((ks << 1) + (lane >> 4)) ^ (mrow & 7);
                ldsm4(a[t], Ab + (uint32_t)(mrow << 8) + (uint32_t)(chn << 4));
            }
#pragma unroll
            for (int p = 0; p < 2; p++) {
                int nrow = wn * 32 + p * 16 + (lane & 15);
                int chn = ((ks << 1) + (lane >> 4)) ^ (nrow & 7);
                ldsm4(b[p], Bb + (uint32_t)(nrow << 8) + (uint32_t)(chn << 4));
            }
#pragma unroll
            for (int t = 0; t < 2; t++)
#pragma unroll
                for (int j = 0; j < 4; j++) {
                    int p = j >> 1, o = j & 1;
                    mma_bf16(cacc[t][j], a[t], b[p][o], b[p][o + 2]);
                }
        }

        // promote this 128-K block with exact fp32 scales
        const float sw = wsc[c];
#pragma unroll
        for (int t = 0; t < 2; t++)
#pragma unroll
            for (int h = 0; h < 2; h++) {
                int row = bm + wm * 32 + t * 16 + h * 8 + (lane >> 2);
                float s = Asc[(size_t)row * nch + c] * sw;
#pragma unroll
                for (int j = 0; j < 4; j++) {
                    full[t][j][2 * h]     = fmaf(s, cacc[t][j][2 * h],     full[t][j][2 * h]);
                    full[t][j][2 * h + 1] = fmaf(s, cacc[t][j][2 * h + 1], full[t][j][2 * h + 1]);
                }
            }
        // (no bottom barrier: next iteration's top __syncthreads protects
        //  stage reuse — the overwrite of stage (c-1)%3 happens after it.)
    }

    // plain fp32 epilogue
#pragma unroll
    for (int t = 0; t < 2; t++)
#pragma unroll
        for (int h = 0; h < 2; h++) {
            int row = bm + wm * 32 + t * 16 + h * 8 + (lane >> 2);
#pragma unroll
            for (int j = 0; j < 4; j++) {
                int col = bn + wn * 32 + j * 8 + (lane & 3) * 2;
                *reinterpret_cast<float2*>(C + (size_t)row * N + col) =
                    make_float2(full[t][j][2 * h], full[t][j][2 * h + 1]);
            }
        }
}

__global__ void __launch_bounds__(512, 1) gemm_plain_kernel(
    const __nv_bfloat16* __restrict__ A, const __nv_bfloat16* __restrict__ B,
    const float* __restrict__ Asc, const float* __restrict__ Wsc,
    float* __restrict__ C, int N, int K)
{
    extern __shared__ char smem[];
    gemm_body(A, B, Asc, Wsc, C, N, K, blockIdx.y, smem);
}

// gate & up in one launch: grid.y in [0,224); y<112 -> gate, else -> up.
__global__ void __launch_bounds__(512, 1) gemm_dual_kernel(
    const __nv_bfloat16* __restrict__ A,
    const __nv_bfloat16* __restrict__ Bg, const __nv_bfloat16* __restrict__ Bu,
    const float* __restrict__ Asc,
    const float* __restrict__ Wg, const float* __restrict__ Wu,
    float* __restrict__ Cg, float* __restrict__ Cu, int K)
{
    extern __shared__ char smem[];
    const int half = II / 128;                        // 112
    const bool is_up = (int)blockIdx.y >= half;
    const __nv_bfloat16* B = is_up ? Bu : Bg;
    const float* W = is_up ? Wu : Wg;
    float* C = is_up ? Cu : Cg;
    const int nb = is_up ? (int)blockIdx.y - half : (int)blockIdx.y;
    gemm_body(A, B, Asc, W, C, II, K, nb, smem);
}

// --------------- side streams / events (static init, created once) ---------
struct AsyncCtx {
    cudaStream_t s1, s2;
    cudaEvent_t e_origin, e_detect, e_up, e_down, e_x;
    AsyncCtx() {
        cudaStreamCreateWithFlags(&s1, cudaStreamNonBlocking);
        cudaStreamCreateWithFlags(&s2, cudaStreamNonBlocking);
        cudaEventCreateWithFlags(&e_origin, cudaEventDisableTiming);
        cudaEventCreateWithFlags(&e_detect, cudaEventDisableTiming);
        cudaEventCreateWithFlags(&e_up, cudaEventDisableTiming);
        cudaEventCreateWithFlags(&e_down, cudaEventDisableTiming);
        cudaEventCreateWithFlags(&e_x, cudaEventDisableTiming);
    }
};
AsyncCtx g_ctx;

}  // namespace

// ============================================================================
extern "C" void kernel_launch(void* const* d_in, const int* in_sizes, int n_in,
                              void* d_out, int out_size) {
    const float* x  = (const float*)d_in[0];
    const void*  gw = d_in[1];
    const float* gs = (const float*)d_in[2];
    const void*  uw = d_in[3];
    const float* us = (const float*)d_in[4];
    const void*  dw = d_in[5];
    const float* ds = (const float*)d_in[6];
    float* out = (float*)d_out;

    __nv_bfloat16 *xb, *gwb, *uwb, *dwb, *hb;
    float *xs, *gate, *up, *hs;
    cudaGetSymbolAddress((void**)&xb,  g_xb);
    cudaGetSymbolAddress((void**)&xs,  g_xs);
    cudaGetSymbolAddress((void**)&gwb, g_gw);
    cudaGetSymbolAddress((void**)&uwb, g_uw);
    cudaGetSymbolAddress((void**)&dwb, g_dw);
    cudaGetSymbolAddress((void**)&gate, g_gate);
    cudaGetSymbolAddress((void**)&up,   g_up);
    cudaGetSymbolAddress((void**)&hb,  g_hb);
    cudaGetSymbolAddress((void**)&hs,  g_hs);

    cudaFuncSetAttribute(gemm_plain_kernel, cudaFuncAttributeMaxDynamicSharedMemorySize, SMEM_SZ);
    cudaFuncSetAttribute(gemm_dual_kernel,  cudaFuncAttributeMaxDynamicSharedMemorySize, SMEM_SZ);

    const size_t n4 = (size_t)II * HH / 4;

    // ---- fork s2 from the capture-origin stream (REQUIRED for capture) ----
    cudaEventRecord(g_ctx.e_origin, 0);
    cudaStreamWaitEvent(g_ctx.s2, g_ctx.e_origin, 0);

    // s2: activation quantization — depends only on x
    fq_x_kernel<<<MM * (HH / QB) / 8, 256, 0, g_ctx.s2>>>(x, xb, xs, HH);
    cudaEventRecord(g_ctx.e_x, g_ctx.s2);

    // main: detect, then fork s1 for up/down weight conversion
    detect_kernel<<<1, 32>>>((const unsigned*)gw);
    cudaEventRecord(g_ctx.e_detect, 0);
    cudaStreamWaitEvent(g_ctx.s1, g_ctx.e_detect, 0);

    convert_w_kernel<<<2048, 256, 0, g_ctx.s1>>>(uw, uwb, n4);
    cudaEventRecord(g_ctx.e_up, g_ctx.s1);
    convert_w_kernel<<<2048, 256, 0, g_ctx.s1>>>(dw, dwb, n4);
    cudaEventRecord(g_ctx.e_down, g_ctx.s1);

    // main: gate weights
    convert_w_kernel<<<2048, 256>>>(gw, gwb, n4);

    // join: up weights + quantized activations needed by the dual GEMM
    cudaStreamWaitEvent(0, g_ctx.e_up, 0);
    cudaStreamWaitEvent(0, g_ctx.e_x, 0);
    gemm_dual_kernel<<<dim3(MM / 128, 2 * (II / 128)), 512, SMEM_SZ>>>(
        xb, gwb, uwb, xs, gs, us, gate, up, HH);

    combine_fq_kernel<<<MM * (II / QB) / 8, 256>>>(gate, up, hb, hs, II);

    // join: down weights needed by the down GEMM (hidden under dual GEMM)
    cudaStreamWaitEvent(0, g_ctx.e_down, 0);
    gemm_plain_kernel<<<dim3(MM / 128, HH / 128), 512, SMEM_SZ>>>(
        hb, dwb, hs, ds, out, HH, II);
}